// round 11
// baseline (speedup 1.0000x reference)
#include <cuda_runtime.h>
#include <cuda_fp16.h>
#include <math.h>
#include <stdint.h>

// Problem constants
#define L 4096
#define H 32
#define EP 32
#define EPH 1024
#define KTAP 4
#define NCH 1024
#define CHUNKS 64
#define CHUNK_LEN 64
#define KTOT 4096          // effective GEMM K = KTAP * EPH

// ---------------- scratch (device globals) ----------------
__device__ __half g_Apad[(L + 3) * EPH];     // padded tap-shift A, fp16
__device__ __half g_WT  [EPH * KTOT];        // conv weights transposed [o][kk], fp16
__device__ float  g_Lam  [L * EPH];
__device__ float  g_Bact [L * EPH];
__device__ float  g_ys   [L * H];
__device__ float4 g_agg  [CHUNKS * NCH];
__device__ float2 g_carry[CHUNKS * NCH];
__device__ float4 g_cA   [NCH];   // (a0x, cos(a0y), sin(a0y), 0)
__device__ float2 g_cB   [NCH];   // Bc complex

__device__ __forceinline__ float siluf(float v) {
    return v / (1.0f + expf(-v));
}

__device__ __forceinline__ uint32_t smem_u32(const void* p) {
    uint32_t a;
    asm("{ .reg .u64 t; cvta.to.shared.u64 t, %1; cvt.u32.u64 %0, t; }" : "=r"(a) : "l"(p));
    return a;
}

#define CP_ASYNC16(dst, src) \
    asm volatile("cp.async.cg.shared.global [%0], [%1], 16;" :: "r"(dst), "l"(src))
#define CP_COMMIT() asm volatile("cp.async.commit_group;" ::: "memory")
#define CP_WAIT1()  asm volatile("cp.async.wait_group 1;" ::: "memory")

__device__ __forceinline__ void ldm_x4(uint32_t* r, uint32_t addr) {
    asm volatile("ldmatrix.sync.aligned.m8n8.x4.shared.b16 {%0,%1,%2,%3}, [%4];"
                 : "=r"(r[0]), "=r"(r[1]), "=r"(r[2]), "=r"(r[3]) : "r"(addr));
}

__device__ __forceinline__ void mma16816(float* c, const uint32_t* a,
                                         uint32_t b0, uint32_t b1) {
    asm volatile(
        "mma.sync.aligned.m16n8k16.row.col.f32.f16.f16.f32 "
        "{%0,%1,%2,%3}, {%4,%5,%6,%7}, {%8,%9}, {%0,%1,%2,%3};"
        : "+f"(c[0]), "+f"(c[1]), "+f"(c[2]), "+f"(c[3])
        : "r"(a[0]), "r"(a[1]), "r"(a[2]), "r"(a[3]), "r"(b0), "r"(b1));
}

// fast elementwise recompute: A = log(1+exp(A0+lam)) (complex), Bu = Bc*Bt*ba
__device__ __forceinline__ void compute_ABu(float lam, float ba, float br, float bi,
                                            float a0x, float cz, float sz,
                                            float bcx, float bcy,
                                            float& Ar, float& Ai,
                                            float& bur, float& bui) {
    float e  = __expf(a0x + lam);
    float wr = fmaf(e, cz, 1.0f);
    float wi = e * sz;
    Ar = 0.5f * __logf(fmaf(wr, wr, wi * wi));
    float r  = __fdividef(wi, wr);
    float r2 = r * r;
    Ai = r * fmaf(r2, fmaf(r2, fmaf(r2, fmaf(r2, fmaf(r2,
            -0.0909090909f, 0.1111111111f), -0.1428571429f),
             0.2f), -0.3333333333f), 1.0f);
    bur = (bcx * br - bcy * bi) * ba;
    bui = (bcx * bi + bcy * br) * ba;
}

// ---------------- K0: precompute constants + zero pad rows -----------------------
__global__ void precompute_kernel(const float* __restrict__ Lre,
                                  const float* __restrict__ Lim,
                                  const float* __restrict__ logstep) {
    int c = threadIdx.x;
    int h = c >> 5;
    float st = expf(logstep[h]);
    float lr = Lre[c], li = Lim[c];
    float zr = lr * st, zi = li * st;
    float e  = expf(zr);
    float a0r = e * cosf(zi);
    float a0i = e * sinf(zi);
    float nr = a0r - 1.0f, ni = a0i;
    float inv = 1.0f / (lr * lr + li * li);
    g_cA[c] = make_float4(a0r, cosf(a0i), sinf(a0i), 0.0f);
    g_cB[c] = make_float2((nr * lr + ni * li) * inv, (ni * lr - nr * li) * inv);

    __half z = __float2half(0.0f);
    g_Apad[0 * EPH + c] = z;
    g_Apad[(L + 1) * EPH + c] = z;
    g_Apad[(L + 2) * EPH + c] = z;
}

// ---------------- K1: B_proj (fp16 into padded buf) ; Lam = silu(x@Wl) -----------
__global__ __launch_bounds__(256) void proj_kernel(const float* __restrict__ x,
                                                   const float* __restrict__ Wb,
                                                   const float* __restrict__ bb,
                                                   const float* __restrict__ Wl,
                                                   const float* __restrict__ bl) {
    __shared__ float xsm[32][33];
    int lb = blockIdx.x * 32;
    int t  = threadIdx.x;
    for (int i = t; i < 32 * 32; i += 256) {
        int r = i >> 5, h = i & 31;
        xsm[r][h] = x[(lb + r) * H + h];
    }
    __syncthreads();

    for (int j = 0; j < 4; j++) {
        int o = t + j * 256;
        {
            float wcol[32];
            #pragma unroll
            for (int h = 0; h < 32; h++) wcol[h] = Wb[h * EPH + o];
            float bv = bb[o];
            for (int r = 0; r < 32; r++) {
                float acc = bv;
                #pragma unroll
                for (int h = 0; h < 32; h++) acc += xsm[r][h] * wcol[h];
                g_Apad[(lb + r + 1) * EPH + o] = __float2half(acc);
            }
        }
        {
            float wcol[32];
            #pragma unroll
            for (int h = 0; h < 32; h++) wcol[h] = Wl[h * EPH + o];
            float bv = bl[o];
            for (int r = 0; r < 32; r++) {
                float acc = bv;
                #pragma unroll
                for (int h = 0; h < 32; h++) acc += xsm[r][h] * wcol[h];
                g_Lam[(lb + r) * EPH + o] = siluf(acc);
            }
        }
    }
}

// ---------------- K1b: transpose conv weights to [o][kk] fp16 --------------------
__global__ __launch_bounds__(256) void wtrans_kernel(const float* __restrict__ cw) {
    __shared__ float tile[32][33];
    int k0 = blockIdx.x * 32;
    int o0 = blockIdx.y * 32;
    int t = threadIdx.x;
    int r = t >> 5, c = t & 31;
    #pragma unroll
    for (int rr = r; rr < 32; rr += 8)
        tile[rr][c] = cw[(size_t)(k0 + rr) * EPH + o0 + c];
    __syncthreads();
    #pragma unroll
    for (int rr = r; rr < 32; rr += 8) {
        float v = tile[c][rr];
        size_t idx = (size_t)(o0 + rr) * KTOT + k0 + c;
        g_WT[idx] = __float2half(v);
    }
}

// ---------------- K2: conv GEMM via mma.sync fp16 (single product) ---------------
// CTA tile 128(m) x 256(n), 8 warps in 2m x 4n, warp tile 64x64.
// 3-stage cp.async pipeline, grid 32x4 = 128 CTAs = single wave.
#define GM 128
#define GN 256
#define GK 32
#define NCHUNK (KTOT / GK)        // 128
#define ROWB 80
#define A_B (128 * ROWB)          // 10240
#define W_B (256 * ROWB)          // 20480
#define BUF_B (A_B + W_B)         // 30720
#define STAGES 3
#define CONV_SMEM (STAGES * BUF_B)  // 92160

__global__ __launch_bounds__(256, 1)
void conv_mma_kernel(const float* __restrict__ cb) {
    extern __shared__ char smem[];
    uint32_t sbase = smem_u32(smem);
    int t = threadIdx.x;
    int lane = t & 31;
    int wid = t >> 5;
    int warp_m = wid & 1;         // 2 warps in m (64 rows each)
    int warp_n = wid >> 1;        // 4 warps in n (64 cols each)
    int lb = blockIdx.x * GM;
    int nb = blockIdx.y * GN;

    float acc[4][8][4];
    #pragma unroll
    for (int i = 0; i < 4; i++)
        #pragma unroll
        for (int j = 0; j < 8; j++)
            #pragma unroll
            for (int k = 0; k < 4; k++) acc[i][j][k] = 0.0f;

    // A load: 128 rows x 64B; thread -> row = t>>1, half = t&1 (32B)
    int arow = t >> 1;
    int ahalf = t & 1;
    uint32_t dApos = arow * ROWB + ahalf * 32;
    // W load: 256 rows x 64B; thread -> row = t (64B = 4x16B)
    uint32_t dWpos = t * ROWB;

    auto issue = [&](int kc) {
        uint32_t base = sbase + (kc % 3) * BUF_B;
        int kg = kc * GK;
        int tap = kg >> 10;
        int i0 = kg & 1023;
        {
            size_t go = (size_t)(lb + arow + tap) * EPH + i0 + ahalf * 16;
            const char* sp = (const char*)(g_Apad + go);
            CP_ASYNC16(base + dApos,      sp);
            CP_ASYNC16(base + dApos + 16, sp + 16);
        }
        {
            size_t go = (size_t)(nb + t) * KTOT + kg;
            const char* sw = (const char*)(g_WT + go);
            uint32_t d = base + A_B + dWpos;
            CP_ASYNC16(d,      sw);
            CP_ASYNC16(d + 16, sw + 16);
            CP_ASYNC16(d + 32, sw + 32);
            CP_ASYNC16(d + 48, sw + 48);
        }
    };

    // ldmatrix lane mapping
    int lr8 = lane & 7;
    int lsel = lane >> 3;
    int lmn = (lsel & 1) * 8 + lr8;
    int lk8 = (lsel >> 1) * 8;

    issue(0); CP_COMMIT();
    issue(1); CP_COMMIT();

    for (int kc = 0; kc < NCHUNK; kc++) {
        CP_WAIT1();
        __syncthreads();
        if (kc + 2 < NCHUNK) issue(kc + 2);
        CP_COMMIT();

        uint32_t base = sbase + (kc % 3) * BUF_B;
        uint32_t Ah = base;
        uint32_t Wt = base + A_B;

        #pragma unroll
        for (int ks = 0; ks < 2; ks++) {
            int kbyte = (ks * 16 + lk8) * 2;
            uint32_t ah[4][4];
            #pragma unroll
            for (int im = 0; im < 4; im++) {
                uint32_t ro = (warp_m * 64 + im * 16 + lmn) * ROWB + kbyte;
                ldm_x4(ah[im], Ah + ro);
            }
            uint32_t w[4][4];
            #pragma unroll
            for (int in4 = 0; in4 < 4; in4++) {
                uint32_t ro = (warp_n * 64 + in4 * 16 + lmn) * ROWB + kbyte;
                ldm_x4(w[in4], Wt + ro);
            }
            #pragma unroll
            for (int in4 = 0; in4 < 4; in4++)
                #pragma unroll
                for (int im = 0; im < 4; im++) {
                    mma16816(acc[im][in4 * 2 + 0], ah[im], w[in4][0], w[in4][2]);
                    mma16816(acc[im][in4 * 2 + 1], ah[im], w[in4][1], w[in4][3]);
                }
        }
    }

    // epilogue: bias + silu, write fp32
    int gid = lane >> 2;
    int tig = lane & 3;
    #pragma unroll
    for (int im = 0; im < 4; im++) {
        int r0 = lb + warp_m * 64 + im * 16 + gid;
        #pragma unroll
        for (int j = 0; j < 8; j++) {
            int col = nb + warp_n * 64 + j * 8 + tig * 2;
            float b0 = cb[col], b1 = cb[col + 1];
            g_Bact[(size_t)r0 * EPH + col]           = siluf(acc[im][j][0] + b0);
            g_Bact[(size_t)r0 * EPH + col + 1]       = siluf(acc[im][j][1] + b1);
            g_Bact[(size_t)(r0 + 8) * EPH + col]     = siluf(acc[im][j][2] + b0);
            g_Bact[(size_t)(r0 + 8) * EPH + col + 1] = siluf(acc[im][j][3] + b1);
        }
    }
}

// ---------------- K3: scan pass 1 (recompute A/Bu inline) ------------------------
__global__ __launch_bounds__(256) void scan_p1_kernel(const float* __restrict__ B) {
    int t = blockIdx.x * blockDim.x + threadIdx.x;   // CHUNKS*NCH = 65536
    int c = t & (NCH - 1);
    int ch = t >> 10;
    int base = ch * CHUNK_LEN;
    int ep = c & 31;

    float4 cA = g_cA[c];
    float2 cB = g_cB[c];

    float Pr = 1.0f, Pi = 0.0f, sr = 0.0f, si = 0.0f;
    for (int i = 0; i < CHUNK_LEN; i++) {
        int l = base + i;
        int idx = l * NCH + c;
        float lam = g_Lam[idx];
        float ba  = g_Bact[idx];
        float br = B[l * 64 + ep * 2 + 0];
        float bi = B[l * 64 + ep * 2 + 1];
        float Ar, Ai, bur, bui;
        compute_ABu(lam, ba, br, bi, cA.x, cA.y, cA.z, cB.x, cB.y, Ar, Ai, bur, bui);

        float nsr = Ar * sr - Ai * si + bur;
        float nsi = Ar * si + Ai * sr + bui;
        sr = nsr; si = nsi;
        float npr = Ar * Pr - Ai * Pi;
        float npi = Ar * Pi + Ai * Pr;
        Pr = npr; Pi = npi;
    }
    g_agg[ch * NCH + c] = make_float4(Pr, Pi, sr, si);
}

// ---------------- K4: scan pass 2 (serial over chunks) ---------------------------
__global__ __launch_bounds__(1024) void scan_p2_kernel() {
    int c = threadIdx.x;
    float cr = 0.0f, ci = 0.0f;
    #pragma unroll
    for (int ch = 0; ch < CHUNKS; ch++) {
        g_carry[ch * NCH + c] = make_float2(cr, ci);
        float4 g = g_agg[ch * NCH + c];
        float nr = g.x * cr - g.y * ci + g.z;
        float ni = g.x * ci + g.y * cr + g.w;
        cr = nr; ci = ni;
    }
}

// ---------------- K5: scan pass 3 (recompute A/Bu, fused ys via atomics) ---------
__global__ __launch_bounds__(256) void scan_p3_kernel(const float* __restrict__ B,
                                                      const float* __restrict__ C) {
    int t = blockIdx.x * blockDim.x + threadIdx.x;
    int c = t & (NCH - 1);
    int ch = t >> 10;
    int base = ch * CHUNK_LEN;
    int ep = c & 31;
    int p = c >> 5;
    int j = c & 31;

    float4 cA = g_cA[c];
    float2 cB = g_cB[c];

    float2 st = g_carry[ch * NCH + c];
    float xr = st.x, xi = st.y;
    for (int i = 0; i < CHUNK_LEN; i++) {
        int l = base + i;
        int idx = l * NCH + c;
        float lam = g_Lam[idx];
        float ba  = g_Bact[idx];
        float br = B[l * 64 + ep * 2 + 0];
        float bi = B[l * 64 + ep * 2 + 1];
        float Ar, Ai, bur, bui;
        compute_ABu(lam, ba, br, bi, cA.x, cA.y, cA.z, cB.x, cB.y, Ar, Ai, bur, bui);

        float nxr = Ar * xr - Ai * xi + bur;
        float nxi = Ar * xi + Ai * xr + bui;
        xr = nxr; xi = nxi;

        float cr = C[l * 64 + p * 2 + 0];
        float ci = C[l * 64 + p * 2 + 1];
        atomicAdd(&g_ys[l * H + j], cr * xr - ci * xi);
    }
}

// ---------------- K8: gating + output projection ---------------------------------
__global__ __launch_bounds__(256) void final_kernel(const float* __restrict__ x,
                                                    const float* __restrict__ Wg,
                                                    const float* __restrict__ bg,
                                                    const float* __restrict__ Wd,
                                                    const float* __restrict__ bd,
                                                    const float* __restrict__ Wo,
                                                    const float* __restrict__ bo,
                                                    float* __restrict__ out) {
    __shared__ float sWg[H * H], sWo[H * H];
    __shared__ float sWd[H], sbg[H], sbo[H];
    __shared__ float sx[8][H], sht[8][H];
    int t = threadIdx.x;
    for (int i = t; i < H * H; i += 256) { sWg[i] = Wg[i]; sWo[i] = Wo[i]; }
    if (t < H) { sWd[t] = Wd[t]; sbg[t] = bg[t]; sbo[t] = bo[t]; }
    int lane = t & 31;
    int w = t >> 5;
    int l = blockIdx.x * 8 + w;
    sx[w][lane] = x[l * H + lane];
    __syncthreads();

    float xg = 0.0f, xd = 0.0f;
    #pragma unroll
    for (int h = 0; h < H; h++) {
        float xv = sx[w][h];
        xg += xv * sWg[h * H + lane];
        xd += xv * sWd[h];
    }
    float gt = siluf(xg + sbg[lane]);
    float d  = log1pf(expf(xd + bd[0]));
    float ysv = g_ys[l * H + lane];
    float xv  = sx[w][lane];
    float ht = (1.0f - gt) * (ysv + d * xv) + gt * xv;
    sht[w][lane] = ht;
    __syncwarp();

    float o = 0.0f;
    #pragma unroll
    for (int h = 0; h < H; h++) o += sht[w][h] * sWo[h * H + lane];
    out[l * H + lane] = o + sbo[lane];
}

// ---------------- launcher -------------------------------------------------------
extern "C" void kernel_launch(void* const* d_in, const int* in_sizes, int n_in,
                              void* d_out, int out_size) {
    const float* x       = (const float*)d_in[0];
    const float* Lre     = (const float*)d_in[1];
    const float* Lim     = (const float*)d_in[2];
    const float* B       = (const float*)d_in[3];
    const float* C       = (const float*)d_in[4];
    const float* logstep = (const float*)d_in[5];
    const float* Wb      = (const float*)d_in[6];
    const float* bb      = (const float*)d_in[7];
    const float* Wl      = (const float*)d_in[8];
    const float* bl      = (const float*)d_in[9];
    const float* cw      = (const float*)d_in[10];
    const float* cb      = (const float*)d_in[11];
    const float* Wg      = (const float*)d_in[12];
    const float* bg      = (const float*)d_in[13];
    const float* Wd      = (const float*)d_in[14];
    const float* bd      = (const float*)d_in[15];
    const float* Wo      = (const float*)d_in[16];
    const float* bo      = (const float*)d_in[17];
    float* out = (float*)d_out;

    cudaFuncSetAttribute(conv_mma_kernel,
                         cudaFuncAttributeMaxDynamicSharedMemorySize, CONV_SMEM);

    void* ys_ptr = nullptr;
    cudaGetSymbolAddress(&ys_ptr, g_ys);
    cudaMemsetAsync(ys_ptr, 0, L * H * sizeof(float));

    precompute_kernel<<<1, 1024>>>(Lre, Lim, logstep);
    proj_kernel<<<L / 32, 256>>>(x, Wb, bb, Wl, bl);

    dim3 wgrid(KTOT / 32, EPH / 32);          // (128, 32)
    wtrans_kernel<<<wgrid, 256>>>(cw);

    dim3 cgrid(L / GM, EPH / GN);             // (32, 4) = 128 CTAs = 1 wave
    conv_mma_kernel<<<cgrid, 256, CONV_SMEM>>>(cb);

    scan_p1_kernel<<<(CHUNKS * NCH) / 256, 256>>>(B);
    scan_p2_kernel<<<1, 1024>>>();
    scan_p3_kernel<<<(CHUNKS * NCH) / 256, 256>>>(B, C);

    final_kernel<<<L / 8, 256>>>(x, Wg, bg, Wd, bd, Wo, bo, out);
}

// round 12
// speedup vs baseline: 1.0526x; 1.0526x over previous
#include <cuda_runtime.h>
#include <cuda_fp16.h>
#include <math.h>
#include <stdint.h>

// Problem constants
#define L 4096
#define H 32
#define EP 32
#define EPH 1024
#define KTAP 4
#define NCH 1024
#define CHUNKS 64
#define CHUNK_LEN 64
#define KTOT 4096          // effective GEMM K = KTAP * EPH

// ---------------- scratch (device globals) ----------------
__device__ __half g_Apad[(L + 3) * EPH];     // padded tap-shift A, fp16
__device__ __half g_WT  [EPH * KTOT];        // conv weights transposed [o][kk], fp16
__device__ float  g_Lam  [L * EPH];
__device__ float  g_Bact [L * EPH];
__device__ float  g_ys   [L * H];
__device__ float4 g_agg  [CHUNKS * NCH];
__device__ float2 g_carry[CHUNKS * NCH];
__device__ float4 g_cA   [NCH];   // (a0x, cos(a0y), sin(a0y), 0)
__device__ float2 g_cB   [NCH];   // Bc complex

__device__ __forceinline__ float siluf(float v) {
    return v / (1.0f + expf(-v));
}

__device__ __forceinline__ uint32_t smem_u32(const void* p) {
    uint32_t a;
    asm("{ .reg .u64 t; cvta.to.shared.u64 t, %1; cvt.u32.u64 %0, t; }" : "=r"(a) : "l"(p));
    return a;
}

#define CP_ASYNC16(dst, src) \
    asm volatile("cp.async.cg.shared.global [%0], [%1], 16;" :: "r"(dst), "l"(src))
#define CP_COMMIT() asm volatile("cp.async.commit_group;" ::: "memory")
#define CP_WAIT1()  asm volatile("cp.async.wait_group 1;" ::: "memory")

__device__ __forceinline__ void ldm_x4(uint32_t* r, uint32_t addr) {
    asm volatile("ldmatrix.sync.aligned.m8n8.x4.shared.b16 {%0,%1,%2,%3}, [%4];"
                 : "=r"(r[0]), "=r"(r[1]), "=r"(r[2]), "=r"(r[3]) : "r"(addr));
}

__device__ __forceinline__ void mma16816(float* c, const uint32_t* a,
                                         uint32_t b0, uint32_t b1) {
    asm volatile(
        "mma.sync.aligned.m16n8k16.row.col.f32.f16.f16.f32 "
        "{%0,%1,%2,%3}, {%4,%5,%6,%7}, {%8,%9}, {%0,%1,%2,%3};"
        : "+f"(c[0]), "+f"(c[1]), "+f"(c[2]), "+f"(c[3])
        : "r"(a[0]), "r"(a[1]), "r"(a[2]), "r"(a[3]), "r"(b0), "r"(b1));
}

// fast elementwise recompute: A = log(1+exp(A0+lam)) (complex), Bu = Bc*Bt*ba
__device__ __forceinline__ void compute_ABu(float lam, float ba, float br, float bi,
                                            float a0x, float cz, float sz,
                                            float bcx, float bcy,
                                            float& Ar, float& Ai,
                                            float& bur, float& bui) {
    float e  = __expf(a0x + lam);
    float wr = fmaf(e, cz, 1.0f);
    float wi = e * sz;
    Ar = 0.5f * __logf(fmaf(wr, wr, wi * wi));
    float r  = __fdividef(wi, wr);
    float r2 = r * r;
    Ai = r * fmaf(r2, fmaf(r2, fmaf(r2, fmaf(r2, fmaf(r2,
            -0.0909090909f, 0.1111111111f), -0.1428571429f),
             0.2f), -0.3333333333f), 1.0f);
    bur = (bcx * br - bcy * bi) * ba;
    bui = (bcx * bi + bcy * br) * ba;
}

// ---------------- K0: precompute constants + zero pad rows -----------------------
__global__ void precompute_kernel(const float* __restrict__ Lre,
                                  const float* __restrict__ Lim,
                                  const float* __restrict__ logstep) {
    int c = threadIdx.x;
    int h = c >> 5;
    float st = expf(logstep[h]);
    float lr = Lre[c], li = Lim[c];
    float zr = lr * st, zi = li * st;
    float e  = expf(zr);
    float a0r = e * cosf(zi);
    float a0i = e * sinf(zi);
    float nr = a0r - 1.0f, ni = a0i;
    float inv = 1.0f / (lr * lr + li * li);
    g_cA[c] = make_float4(a0r, cosf(a0i), sinf(a0i), 0.0f);
    g_cB[c] = make_float2((nr * lr + ni * li) * inv, (ni * lr - nr * li) * inv);

    __half z = __float2half(0.0f);
    g_Apad[0 * EPH + c] = z;
    g_Apad[(L + 1) * EPH + c] = z;
    g_Apad[(L + 2) * EPH + c] = z;
}

// ---------------- K1: B_proj (fp16 into padded buf) ; Lam = silu(x@Wl) -----------
// grid (L/32, 2): o-halves split across blockIdx.y for 2x parallelism
__global__ __launch_bounds__(256) void proj_kernel(const float* __restrict__ x,
                                                   const float* __restrict__ Wb,
                                                   const float* __restrict__ bb,
                                                   const float* __restrict__ Wl,
                                                   const float* __restrict__ bl) {
    __shared__ float xsm[32][33];
    int lb = blockIdx.x * 32;
    int ob = blockIdx.y * 512;
    int t  = threadIdx.x;
    for (int i = t; i < 32 * 32; i += 256) {
        int r = i >> 5, h = i & 31;
        xsm[r][h] = x[(lb + r) * H + h];
    }
    __syncthreads();

    for (int j = 0; j < 2; j++) {
        int o = ob + t + j * 256;
        {
            float wcol[32];
            #pragma unroll
            for (int h = 0; h < 32; h++) wcol[h] = Wb[h * EPH + o];
            float bv = bb[o];
            for (int r = 0; r < 32; r++) {
                float acc = bv;
                #pragma unroll
                for (int h = 0; h < 32; h++) acc += xsm[r][h] * wcol[h];
                g_Apad[(lb + r + 1) * EPH + o] = __float2half(acc);
            }
        }
        {
            float wcol[32];
            #pragma unroll
            for (int h = 0; h < 32; h++) wcol[h] = Wl[h * EPH + o];
            float bv = bl[o];
            for (int r = 0; r < 32; r++) {
                float acc = bv;
                #pragma unroll
                for (int h = 0; h < 32; h++) acc += xsm[r][h] * wcol[h];
                g_Lam[(lb + r) * EPH + o] = siluf(acc);
            }
        }
    }
}

// ---------------- K1b: transpose conv weights to [o][kk] fp16 --------------------
__global__ __launch_bounds__(256) void wtrans_kernel(const float* __restrict__ cw) {
    __shared__ float tile[32][33];
    int k0 = blockIdx.x * 32;
    int o0 = blockIdx.y * 32;
    int t = threadIdx.x;
    int r = t >> 5, c = t & 31;
    #pragma unroll
    for (int rr = r; rr < 32; rr += 8)
        tile[rr][c] = cw[(size_t)(k0 + rr) * EPH + o0 + c];
    __syncthreads();
    #pragma unroll
    for (int rr = r; rr < 32; rr += 8) {
        float v = tile[c][rr];
        size_t idx = (size_t)(o0 + rr) * KTOT + k0 + c;
        g_WT[idx] = __float2half(v);
    }
}

// ---------------- K2: conv GEMM via mma.sync fp16 (single product) ---------------
// CTA tile 128x128, 8 warps (4m x 2n), warp tile 32x64.
// GK=64 chunks (64 total), 3-stage cp.async pipeline, 2 CTAs/SM.
#define GM 128
#define GN 128
#define GK 64
#define NCHUNK (KTOT / GK)        // 64
#define ROWB 144                  // 128B data + 16B pad (4-bank rotation/row)
#define TILE_B (128 * ROWB)       // 18432
#define BUF_B (2 * TILE_B)        // A, W = 36864
#define STAGES 3
#define CONV_SMEM (STAGES * BUF_B)  // 110592 -> 2 CTAs/SM (216KB of 228)

__global__ __launch_bounds__(256, 2)
void conv_mma_kernel(const float* __restrict__ cb) {
    extern __shared__ char smem[];
    uint32_t sbase = smem_u32(smem);
    int t = threadIdx.x;
    int lane = t & 31;
    int wid = t >> 5;
    int warp_m = wid & 3;
    int warp_n = wid >> 2;
    int lb = blockIdx.x * GM;
    int nb = blockIdx.y * GN;

    float acc[2][8][4];
    #pragma unroll
    for (int i = 0; i < 2; i++)
        #pragma unroll
        for (int j = 0; j < 8; j++)
            #pragma unroll
            for (int k = 0; k < 4; k++) acc[i][j][k] = 0.0f;

    // load mapping: thread -> row = t>>1, half = t&1 (64B each, 4x16B)
    int lrow = t >> 1;
    int lhalf = t & 1;
    uint32_t dpos = lrow * ROWB + lhalf * 64;

    auto issue = [&](int kc) {
        uint32_t base = sbase + (kc % 3) * BUF_B;
        int kg = kc * GK;
        int tap = kg >> 10;
        int i0 = kg & 1023;
        {
            size_t go = (size_t)(lb + lrow + tap) * EPH + i0 + lhalf * 32;
            const char* sp = (const char*)(g_Apad + go);
            CP_ASYNC16(base + dpos,      sp);
            CP_ASYNC16(base + dpos + 16, sp + 16);
            CP_ASYNC16(base + dpos + 32, sp + 32);
            CP_ASYNC16(base + dpos + 48, sp + 48);
        }
        {
            size_t go = (size_t)(nb + lrow) * KTOT + kg + lhalf * 32;
            const char* sw = (const char*)(g_WT + go);
            uint32_t d = base + TILE_B + dpos;
            CP_ASYNC16(d,      sw);
            CP_ASYNC16(d + 16, sw + 16);
            CP_ASYNC16(d + 32, sw + 32);
            CP_ASYNC16(d + 48, sw + 48);
        }
    };

    // ldmatrix lane mapping
    int lr8 = lane & 7;
    int lsel = lane >> 3;
    int lmn = (lsel & 1) * 8 + lr8;
    int lk8 = (lsel >> 1) * 8;

    issue(0); CP_COMMIT();
    issue(1); CP_COMMIT();

    for (int kc = 0; kc < NCHUNK; kc++) {
        CP_WAIT1();
        __syncthreads();
        if (kc + 2 < NCHUNK) issue(kc + 2);
        CP_COMMIT();

        uint32_t base = sbase + (kc % 3) * BUF_B;
        uint32_t Ah = base;
        uint32_t Wt = base + TILE_B;

        #pragma unroll
        for (int ks = 0; ks < 4; ks++) {
            int kbyte = ks * 32 + lk8 * 2;
            uint32_t ah[2][4];
            #pragma unroll
            for (int im = 0; im < 2; im++) {
                uint32_t ro = (warp_m * 32 + im * 16 + lmn) * ROWB + kbyte;
                ldm_x4(ah[im], Ah + ro);
            }
            uint32_t w[4][4];
            #pragma unroll
            for (int in4 = 0; in4 < 4; in4++) {
                uint32_t ro = (warp_n * 64 + in4 * 16 + lmn) * ROWB + kbyte;
                ldm_x4(w[in4], Wt + ro);
            }
            #pragma unroll
            for (int in4 = 0; in4 < 4; in4++)
                #pragma unroll
                for (int im = 0; im < 2; im++) {
                    mma16816(acc[im][in4 * 2 + 0], ah[im], w[in4][0], w[in4][2]);
                    mma16816(acc[im][in4 * 2 + 1], ah[im], w[in4][1], w[in4][3]);
                }
        }
    }

    // epilogue: bias + silu, write fp32
    int gid = lane >> 2;
    int tig = lane & 3;
    #pragma unroll
    for (int im = 0; im < 2; im++) {
        int r0 = lb + warp_m * 32 + im * 16 + gid;
        #pragma unroll
        for (int j = 0; j < 8; j++) {
            int col = nb + warp_n * 64 + j * 8 + tig * 2;
            float b0 = cb[col], b1 = cb[col + 1];
            g_Bact[(size_t)r0 * EPH + col]           = siluf(acc[im][j][0] + b0);
            g_Bact[(size_t)r0 * EPH + col + 1]       = siluf(acc[im][j][1] + b1);
            g_Bact[(size_t)(r0 + 8) * EPH + col]     = siluf(acc[im][j][2] + b0);
            g_Bact[(size_t)(r0 + 8) * EPH + col + 1] = siluf(acc[im][j][3] + b1);
        }
    }
}

// ---------------- K3: scan pass 1 (recompute A/Bu inline) ------------------------
__global__ __launch_bounds__(256) void scan_p1_kernel(const float* __restrict__ B) {
    int t = blockIdx.x * blockDim.x + threadIdx.x;   // CHUNKS*NCH = 65536
    int c = t & (NCH - 1);
    int ch = t >> 10;
    int base = ch * CHUNK_LEN;
    int ep = c & 31;

    float4 cA = g_cA[c];
    float2 cB = g_cB[c];

    float Pr = 1.0f, Pi = 0.0f, sr = 0.0f, si = 0.0f;
    for (int i = 0; i < CHUNK_LEN; i++) {
        int l = base + i;
        int idx = l * NCH + c;
        float lam = g_Lam[idx];
        float ba  = g_Bact[idx];
        float br = B[l * 64 + ep * 2 + 0];
        float bi = B[l * 64 + ep * 2 + 1];
        float Ar, Ai, bur, bui;
        compute_ABu(lam, ba, br, bi, cA.x, cA.y, cA.z, cB.x, cB.y, Ar, Ai, bur, bui);

        float nsr = Ar * sr - Ai * si + bur;
        float nsi = Ar * si + Ai * sr + bui;
        sr = nsr; si = nsi;
        float npr = Ar * Pr - Ai * Pi;
        float npi = Ar * Pi + Ai * Pr;
        Pr = npr; Pi = npi;
    }
    g_agg[ch * NCH + c] = make_float4(Pr, Pi, sr, si);
}

// ---------------- K4: scan pass 2 (serial over chunks) ---------------------------
__global__ __launch_bounds__(1024) void scan_p2_kernel() {
    int c = threadIdx.x;
    float cr = 0.0f, ci = 0.0f;
    #pragma unroll
    for (int ch = 0; ch < CHUNKS; ch++) {
        g_carry[ch * NCH + c] = make_float2(cr, ci);
        float4 g = g_agg[ch * NCH + c];
        float nr = g.x * cr - g.y * ci + g.z;
        float ni = g.x * ci + g.y * cr + g.w;
        cr = nr; ci = ni;
    }
}

// ---------------- K5: scan pass 3 (recompute A/Bu, fused ys via atomics) ---------
__global__ __launch_bounds__(256) void scan_p3_kernel(const float* __restrict__ B,
                                                      const float* __restrict__ C) {
    int t = blockIdx.x * blockDim.x + threadIdx.x;
    int c = t & (NCH - 1);
    int ch = t >> 10;
    int base = ch * CHUNK_LEN;
    int ep = c & 31;
    int p = c >> 5;
    int j = c & 31;

    float4 cA = g_cA[c];
    float2 cB = g_cB[c];

    float2 st = g_carry[ch * NCH + c];
    float xr = st.x, xi = st.y;
    for (int i = 0; i < CHUNK_LEN; i++) {
        int l = base + i;
        int idx = l * NCH + c;
        float lam = g_Lam[idx];
        float ba  = g_Bact[idx];
        float br = B[l * 64 + ep * 2 + 0];
        float bi = B[l * 64 + ep * 2 + 1];
        float Ar, Ai, bur, bui;
        compute_ABu(lam, ba, br, bi, cA.x, cA.y, cA.z, cB.x, cB.y, Ar, Ai, bur, bui);

        float nxr = Ar * xr - Ai * xi + bur;
        float nxi = Ar * xi + Ai * xr + bui;
        xr = nxr; xi = nxi;

        float cr = C[l * 64 + p * 2 + 0];
        float ci = C[l * 64 + p * 2 + 1];
        atomicAdd(&g_ys[l * H + j], cr * xr - ci * xi);
    }
}

// ---------------- K8: gating + output projection ---------------------------------
__global__ __launch_bounds__(256) void final_kernel(const float* __restrict__ x,
                                                    const float* __restrict__ Wg,
                                                    const float* __restrict__ bg,
                                                    const float* __restrict__ Wd,
                                                    const float* __restrict__ bd,
                                                    const float* __restrict__ Wo,
                                                    const float* __restrict__ bo,
                                                    float* __restrict__ out) {
    __shared__ float sWg[H * H], sWo[H * H];
    __shared__ float sWd[H], sbg[H], sbo[H];
    __shared__ float sx[8][H], sht[8][H];
    int t = threadIdx.x;
    for (int i = t; i < H * H; i += 256) { sWg[i] = Wg[i]; sWo[i] = Wo[i]; }
    if (t < H) { sWd[t] = Wd[t]; sbg[t] = bg[t]; sbo[t] = bo[t]; }
    int lane = t & 31;
    int w = t >> 5;
    int l = blockIdx.x * 8 + w;
    sx[w][lane] = x[l * H + lane];
    __syncthreads();

    float xg = 0.0f, xd = 0.0f;
    #pragma unroll
    for (int h = 0; h < H; h++) {
        float xv = sx[w][h];
        xg += xv * sWg[h * H + lane];
        xd += xv * sWd[h];
    }
    float gt = siluf(xg + sbg[lane]);
    float d  = log1pf(expf(xd + bd[0]));
    float ysv = g_ys[l * H + lane];
    float xv  = sx[w][lane];
    float ht = (1.0f - gt) * (ysv + d * xv) + gt * xv;
    sht[w][lane] = ht;
    __syncwarp();

    float o = 0.0f;
    #pragma unroll
    for (int h = 0; h < H; h++) o += sht[w][h] * sWo[h * H + lane];
    out[l * H + lane] = o + sbo[lane];
}

// ---------------- launcher -------------------------------------------------------
extern "C" void kernel_launch(void* const* d_in, const int* in_sizes, int n_in,
                              void* d_out, int out_size) {
    const float* x       = (const float*)d_in[0];
    const float* Lre     = (const float*)d_in[1];
    const float* Lim     = (const float*)d_in[2];
    const float* B       = (const float*)d_in[3];
    const float* C       = (const float*)d_in[4];
    const float* logstep = (const float*)d_in[5];
    const float* Wb      = (const float*)d_in[6];
    const float* bb      = (const float*)d_in[7];
    const float* Wl      = (const float*)d_in[8];
    const float* bl      = (const float*)d_in[9];
    const float* cw      = (const float*)d_in[10];
    const float* cb      = (const float*)d_in[11];
    const float* Wg      = (const float*)d_in[12];
    const float* bg      = (const float*)d_in[13];
    const float* Wd      = (const float*)d_in[14];
    const float* bd      = (const float*)d_in[15];
    const float* Wo      = (const float*)d_in[16];
    const float* bo      = (const float*)d_in[17];
    float* out = (float*)d_out;

    cudaFuncSetAttribute(conv_mma_kernel,
                         cudaFuncAttributeMaxDynamicSharedMemorySize, CONV_SMEM);

    void* ys_ptr = nullptr;
    cudaGetSymbolAddress(&ys_ptr, g_ys);
    cudaMemsetAsync(ys_ptr, 0, L * H * sizeof(float));

    precompute_kernel<<<1, 1024>>>(Lre, Lim, logstep);

    dim3 pgrid(L / 32, 2);                    // 256 blocks
    proj_kernel<<<pgrid, 256>>>(x, Wb, bb, Wl, bl);

    dim3 wgrid(KTOT / 32, EPH / 32);          // (128, 32)
    wtrans_kernel<<<wgrid, 256>>>(cw);

    dim3 cgrid(L / GM, EPH / GN);             // (32, 8) = 256 CTAs
    conv_mma_kernel<<<cgrid, 256, CONV_SMEM>>>(cb);

    scan_p1_kernel<<<(CHUNKS * NCH) / 256, 256>>>(B);
    scan_p2_kernel<<<1, 1024>>>();
    scan_p3_kernel<<<(CHUNKS * NCH) / 256, 256>>>(B, C);

    final_kernel<<<L / 8, 256>>>(x, Wg, bg, Wd, bd, Wo, bo, out);
}

// round 13
// speedup vs baseline: 1.1647x; 1.1065x over previous
#include <cuda_runtime.h>
#include <cuda_fp16.h>
#include <math.h>
#include <stdint.h>

// Problem constants
#define L 4096
#define H 32
#define EP 32
#define EPH 1024
#define KTAP 4
#define NCH 1024
#define CHUNKS 64
#define CHUNK_LEN 64
#define KTOT 4096          // effective GEMM K = KTAP * EPH

// ---------------- scratch (device globals) ----------------
__device__ __half g_Apad[(L + 3) * EPH];     // padded tap-shift A, fp16
__device__ __half g_WT  [EPH * KTOT];        // conv weights transposed [o][kk], fp16
__device__ float  g_Lam  [L * EPH];
__device__ float  g_Bact [L * EPH];
__device__ float  g_ys   [L * H];
__device__ float4 g_agg  [CHUNKS * NCH];
__device__ float2 g_carry[CHUNKS * NCH];
__device__ float4 g_cA   [NCH];   // (a0x, cos(a0y), sin(a0y), 0)
__device__ float2 g_cB   [NCH];   // Bc complex

__device__ __forceinline__ float siluf(float v) {
    return v / (1.0f + expf(-v));
}

__device__ __forceinline__ uint32_t smem_u32(const void* p) {
    uint32_t a;
    asm("{ .reg .u64 t; cvta.to.shared.u64 t, %1; cvt.u32.u64 %0, t; }" : "=r"(a) : "l"(p));
    return a;
}

#define CP_ASYNC16(dst, src) \
    asm volatile("cp.async.cg.shared.global [%0], [%1], 16;" :: "r"(dst), "l"(src))
#define CP_COMMIT() asm volatile("cp.async.commit_group;" ::: "memory")
#define CP_WAIT2()  asm volatile("cp.async.wait_group 2;" ::: "memory")

__device__ __forceinline__ void ldm_x4(uint32_t* r, uint32_t addr) {
    asm volatile("ldmatrix.sync.aligned.m8n8.x4.shared.b16 {%0,%1,%2,%3}, [%4];"
                 : "=r"(r[0]), "=r"(r[1]), "=r"(r[2]), "=r"(r[3]) : "r"(addr));
}

__device__ __forceinline__ void mma16816(float* c, const uint32_t* a,
                                         uint32_t b0, uint32_t b1) {
    asm volatile(
        "mma.sync.aligned.m16n8k16.row.col.f32.f16.f16.f32 "
        "{%0,%1,%2,%3}, {%4,%5,%6,%7}, {%8,%9}, {%0,%1,%2,%3};"
        : "+f"(c[0]), "+f"(c[1]), "+f"(c[2]), "+f"(c[3])
        : "r"(a[0]), "r"(a[1]), "r"(a[2]), "r"(a[3]), "r"(b0), "r"(b1));
}

// fast elementwise recompute: A = log(1+exp(A0+lam)) (complex), Bu = Bc*Bt*ba
__device__ __forceinline__ void compute_ABu(float lam, float ba, float br, float bi,
                                            float a0x, float cz, float sz,
                                            float bcx, float bcy,
                                            float& Ar, float& Ai,
                                            float& bur, float& bui) {
    float e  = __expf(a0x + lam);
    float wr = fmaf(e, cz, 1.0f);
    float wi = e * sz;
    Ar = 0.5f * __logf(fmaf(wr, wr, wi * wi));
    float r  = __fdividef(wi, wr);
    float r2 = r * r;
    Ai = r * fmaf(r2, fmaf(r2, fmaf(r2, fmaf(r2, fmaf(r2,
            -0.0909090909f, 0.1111111111f), -0.1428571429f),
             0.2f), -0.3333333333f), 1.0f);
    bur = (bcx * br - bcy * bi) * ba;
    bui = (bcx * bi + bcy * br) * ba;
}

// ---------------- K0: precompute constants + zero pad rows -----------------------
__global__ void precompute_kernel(const float* __restrict__ Lre,
                                  const float* __restrict__ Lim,
                                  const float* __restrict__ logstep) {
    int c = threadIdx.x;
    int h = c >> 5;
    float st = expf(logstep[h]);
    float lr = Lre[c], li = Lim[c];
    float zr = lr * st, zi = li * st;
    float e  = expf(zr);
    float a0r = e * cosf(zi);
    float a0i = e * sinf(zi);
    float nr = a0r - 1.0f, ni = a0i;
    float inv = 1.0f / (lr * lr + li * li);
    g_cA[c] = make_float4(a0r, cosf(a0i), sinf(a0i), 0.0f);
    g_cB[c] = make_float2((nr * lr + ni * li) * inv, (ni * lr - nr * li) * inv);

    __half z = __float2half(0.0f);
    g_Apad[0 * EPH + c] = z;
    g_Apad[(L + 1) * EPH + c] = z;
    g_Apad[(L + 2) * EPH + c] = z;
}

// ---------------- K1: B_proj (fp16 into padded buf) ; Lam = silu(x@Wl) -----------
// grid (L/32, 2): o-halves split across blockIdx.y for 2x parallelism
__global__ __launch_bounds__(256) void proj_kernel(const float* __restrict__ x,
                                                   const float* __restrict__ Wb,
                                                   const float* __restrict__ bb,
                                                   const float* __restrict__ Wl,
                                                   const float* __restrict__ bl) {
    __shared__ float xsm[32][33];
    int lb = blockIdx.x * 32;
    int ob = blockIdx.y * 512;
    int t  = threadIdx.x;
    for (int i = t; i < 32 * 32; i += 256) {
        int r = i >> 5, h = i & 31;
        xsm[r][h] = x[(lb + r) * H + h];
    }
    __syncthreads();

    for (int j = 0; j < 2; j++) {
        int o = ob + t + j * 256;
        {
            float wcol[32];
            #pragma unroll
            for (int h = 0; h < 32; h++) wcol[h] = Wb[h * EPH + o];
            float bv = bb[o];
            for (int r = 0; r < 32; r++) {
                float acc = bv;
                #pragma unroll
                for (int h = 0; h < 32; h++) acc += xsm[r][h] * wcol[h];
                g_Apad[(lb + r + 1) * EPH + o] = __float2half(acc);
            }
        }
        {
            float wcol[32];
            #pragma unroll
            for (int h = 0; h < 32; h++) wcol[h] = Wl[h * EPH + o];
            float bv = bl[o];
            for (int r = 0; r < 32; r++) {
                float acc = bv;
                #pragma unroll
                for (int h = 0; h < 32; h++) acc += xsm[r][h] * wcol[h];
                g_Lam[(lb + r) * EPH + o] = siluf(acc);
            }
        }
    }
}

// ---------------- K1b: transpose conv weights to [o][kk] fp16 --------------------
__global__ __launch_bounds__(256) void wtrans_kernel(const float* __restrict__ cw) {
    __shared__ float tile[32][33];
    int k0 = blockIdx.x * 32;
    int o0 = blockIdx.y * 32;
    int t = threadIdx.x;
    int r = t >> 5, c = t & 31;
    #pragma unroll
    for (int rr = r; rr < 32; rr += 8)
        tile[rr][c] = cw[(size_t)(k0 + rr) * EPH + o0 + c];
    __syncthreads();
    #pragma unroll
    for (int rr = r; rr < 32; rr += 8) {
        float v = tile[c][rr];
        size_t idx = (size_t)(o0 + rr) * KTOT + k0 + c;
        g_WT[idx] = __float2half(v);
    }
}

// ---------------- K2: conv GEMM via mma.sync fp16 (single product) ---------------
// R8 winner config exactly: 128x128 tile, 8 warps (4m x 2n), GK=32,
// ROWB=80, 4-stage cp.async (wait_group 2), 2 CTAs/SM.
#define GM 128
#define GN 128
#define GK 32
#define NCHUNK (KTOT / GK)        // 128
#define ROWB 80
#define TILE_B (128 * ROWB)
#define BUF_B (2 * TILE_B)
#define STAGES 4
#define CONV_SMEM (STAGES * BUF_B)  // 81920

__global__ __launch_bounds__(256, 2)
void conv_mma_kernel(const float* __restrict__ cb) {
    extern __shared__ char smem[];
    uint32_t sbase = smem_u32(smem);
    int t = threadIdx.x;
    int lane = t & 31;
    int wid = t >> 5;
    int warp_m = wid & 3;
    int warp_n = wid >> 2;
    int lb = blockIdx.x * GM;
    int nb = blockIdx.y * GN;

    float acc[2][8][4];
    #pragma unroll
    for (int i = 0; i < 2; i++)
        #pragma unroll
        for (int j = 0; j < 8; j++)
            #pragma unroll
            for (int k = 0; k < 4; k++) acc[i][j][k] = 0.0f;

    int lrow = t >> 1;
    int lhalf = t & 1;
    uint32_t dpos = lrow * ROWB + lhalf * 32;

    auto issue = [&](int kc) {
        uint32_t base = sbase + (kc & 3) * BUF_B;
        int kg = kc * GK;
        int tap = kg >> 10;
        int i0 = kg & 1023;
        {
            size_t go = (size_t)(lb + lrow + tap) * EPH + i0 + lhalf * 16;
            const char* sp = (const char*)(g_Apad + go);
            CP_ASYNC16(base + dpos,      sp);
            CP_ASYNC16(base + dpos + 16, sp + 16);
        }
        {
            size_t go = (size_t)(nb + lrow) * KTOT + kg + lhalf * 16;
            const char* sw = (const char*)(g_WT + go);
            CP_ASYNC16(base + TILE_B + dpos,      sw);
            CP_ASYNC16(base + TILE_B + dpos + 16, sw + 16);
        }
    };

    int lr8 = lane & 7;
    int lsel = lane >> 3;
    int lmn = (lsel & 1) * 8 + lr8;
    int lk8 = (lsel >> 1) * 8;

    issue(0); CP_COMMIT();
    issue(1); CP_COMMIT();
    issue(2); CP_COMMIT();

    for (int kc = 0; kc < NCHUNK; kc++) {
        CP_WAIT2();
        __syncthreads();
        if (kc + 3 < NCHUNK) issue(kc + 3);
        CP_COMMIT();

        uint32_t base = sbase + (kc & 3) * BUF_B;
        uint32_t Ah = base;
        uint32_t Wt = base + TILE_B;

        #pragma unroll
        for (int ks = 0; ks < 2; ks++) {
            int kbyte = (ks * 16 + lk8) * 2;
            uint32_t ah[2][4];
            #pragma unroll
            for (int im = 0; im < 2; im++) {
                uint32_t ro = (warp_m * 32 + im * 16 + lmn) * ROWB + kbyte;
                ldm_x4(ah[im], Ah + ro);
            }
            uint32_t w[4][4];
            #pragma unroll
            for (int in4 = 0; in4 < 4; in4++) {
                uint32_t ro = (warp_n * 64 + in4 * 16 + lmn) * ROWB + kbyte;
                ldm_x4(w[in4], Wt + ro);
            }
            #pragma unroll
            for (int in4 = 0; in4 < 4; in4++)
                #pragma unroll
                for (int im = 0; im < 2; im++) {
                    mma16816(acc[im][in4 * 2 + 0], ah[im], w[in4][0], w[in4][2]);
                    mma16816(acc[im][in4 * 2 + 1], ah[im], w[in4][1], w[in4][3]);
                }
        }
    }

    int gid = lane >> 2;
    int tig = lane & 3;
    #pragma unroll
    for (int im = 0; im < 2; im++) {
        int r0 = lb + warp_m * 32 + im * 16 + gid;
        #pragma unroll
        for (int j = 0; j < 8; j++) {
            int col = nb + warp_n * 64 + j * 8 + tig * 2;
            float b0 = cb[col], b1 = cb[col + 1];
            g_Bact[(size_t)r0 * EPH + col]           = siluf(acc[im][j][0] + b0);
            g_Bact[(size_t)r0 * EPH + col + 1]       = siluf(acc[im][j][1] + b1);
            g_Bact[(size_t)(r0 + 8) * EPH + col]     = siluf(acc[im][j][2] + b0);
            g_Bact[(size_t)(r0 + 8) * EPH + col + 1] = siluf(acc[im][j][3] + b1);
        }
    }
}

// ---------------- K3: scan pass 1 (recompute A/Bu inline) ------------------------
__global__ __launch_bounds__(256) void scan_p1_kernel(const float* __restrict__ B) {
    int t = blockIdx.x * blockDim.x + threadIdx.x;   // CHUNKS*NCH = 65536
    int c = t & (NCH - 1);
    int ch = t >> 10;
    int base = ch * CHUNK_LEN;
    int ep = c & 31;

    float4 cA = g_cA[c];
    float2 cB = g_cB[c];

    float Pr = 1.0f, Pi = 0.0f, sr = 0.0f, si = 0.0f;
    for (int i = 0; i < CHUNK_LEN; i++) {
        int l = base + i;
        int idx = l * NCH + c;
        float lam = g_Lam[idx];
        float ba  = g_Bact[idx];
        float br = B[l * 64 + ep * 2 + 0];
        float bi = B[l * 64 + ep * 2 + 1];
        float Ar, Ai, bur, bui;
        compute_ABu(lam, ba, br, bi, cA.x, cA.y, cA.z, cB.x, cB.y, Ar, Ai, bur, bui);

        float nsr = Ar * sr - Ai * si + bur;
        float nsi = Ar * si + Ai * sr + bui;
        sr = nsr; si = nsi;
        float npr = Ar * Pr - Ai * Pi;
        float npi = Ar * Pi + Ai * Pr;
        Pr = npr; Pi = npi;
    }
    g_agg[ch * NCH + c] = make_float4(Pr, Pi, sr, si);
}

// ---------------- K4: scan pass 2 (serial over chunks) ---------------------------
__global__ __launch_bounds__(1024) void scan_p2_kernel() {
    int c = threadIdx.x;
    float cr = 0.0f, ci = 0.0f;
    #pragma unroll
    for (int ch = 0; ch < CHUNKS; ch++) {
        g_carry[ch * NCH + c] = make_float2(cr, ci);
        float4 g = g_agg[ch * NCH + c];
        float nr = g.x * cr - g.y * ci + g.z;
        float ni = g.x * ci + g.y * cr + g.w;
        cr = nr; ci = ni;
    }
}

// ---------------- K5: scan pass 3 (recompute A/Bu, fused ys via atomics) ---------
__global__ __launch_bounds__(256) void scan_p3_kernel(const float* __restrict__ B,
                                                      const float* __restrict__ C) {
    int t = blockIdx.x * blockDim.x + threadIdx.x;
    int c = t & (NCH - 1);
    int ch = t >> 10;
    int base = ch * CHUNK_LEN;
    int ep = c & 31;
    int p = c >> 5;
    int j = c & 31;

    float4 cA = g_cA[c];
    float2 cB = g_cB[c];

    float2 st = g_carry[ch * NCH + c];
    float xr = st.x, xi = st.y;
    for (int i = 0; i < CHUNK_LEN; i++) {
        int l = base + i;
        int idx = l * NCH + c;
        float lam = g_Lam[idx];
        float ba  = g_Bact[idx];
        float br = B[l * 64 + ep * 2 + 0];
        float bi = B[l * 64 + ep * 2 + 1];
        float Ar, Ai, bur, bui;
        compute_ABu(lam, ba, br, bi, cA.x, cA.y, cA.z, cB.x, cB.y, Ar, Ai, bur, bui);

        float nxr = Ar * xr - Ai * xi + bur;
        float nxi = Ar * xi + Ai * xr + bui;
        xr = nxr; xi = nxi;

        float cr = C[l * 64 + p * 2 + 0];
        float ci = C[l * 64 + p * 2 + 1];
        atomicAdd(&g_ys[l * H + j], cr * xr - ci * xi);
    }
}

// ---------------- K8: gating + output projection ---------------------------------
__global__ __launch_bounds__(256) void final_kernel(const float* __restrict__ x,
                                                    const float* __restrict__ Wg,
                                                    const float* __restrict__ bg,
                                                    const float* __restrict__ Wd,
                                                    const float* __restrict__ bd,
                                                    const float* __restrict__ Wo,
                                                    const float* __restrict__ bo,
                                                    float* __restrict__ out) {
    __shared__ float sWg[H * H], sWo[H * H];
    __shared__ float sWd[H], sbg[H], sbo[H];
    __shared__ float sx[8][H], sht[8][H];
    int t = threadIdx.x;
    for (int i = t; i < H * H; i += 256) { sWg[i] = Wg[i]; sWo[i] = Wo[i]; }
    if (t < H) { sWd[t] = Wd[t]; sbg[t] = bg[t]; sbo[t] = bo[t]; }
    int lane = t & 31;
    int w = t >> 5;
    int l = blockIdx.x * 8 + w;
    sx[w][lane] = x[l * H + lane];
    __syncthreads();

    float xg = 0.0f, xd = 0.0f;
    #pragma unroll
    for (int h = 0; h < H; h++) {
        float xv = sx[w][h];
        xg += xv * sWg[h * H + lane];
        xd += xv * sWd[h];
    }
    float gt = siluf(xg + sbg[lane]);
    float d  = log1pf(expf(xd + bd[0]));
    float ysv = g_ys[l * H + lane];
    float xv  = sx[w][lane];
    float ht = (1.0f - gt) * (ysv + d * xv) + gt * xv;
    sht[w][lane] = ht;
    __syncwarp();

    float o = 0.0f;
    #pragma unroll
    for (int h = 0; h < H; h++) o += sht[w][h] * sWo[h * H + lane];
    out[l * H + lane] = o + sbo[lane];
}

// ---------------- launcher -------------------------------------------------------
extern "C" void kernel_launch(void* const* d_in, const int* in_sizes, int n_in,
                              void* d_out, int out_size) {
    const float* x       = (const float*)d_in[0];
    const float* Lre     = (const float*)d_in[1];
    const float* Lim     = (const float*)d_in[2];
    const float* B       = (const float*)d_in[3];
    const float* C       = (const float*)d_in[4];
    const float* logstep = (const float*)d_in[5];
    const float* Wb      = (const float*)d_in[6];
    const float* bb      = (const float*)d_in[7];
    const float* Wl      = (const float*)d_in[8];
    const float* bl      = (const float*)d_in[9];
    const float* cw      = (const float*)d_in[10];
    const float* cb      = (const float*)d_in[11];
    const float* Wg      = (const float*)d_in[12];
    const float* bg      = (const float*)d_in[13];
    const float* Wd      = (const float*)d_in[14];
    const float* bd      = (const float*)d_in[15];
    const float* Wo      = (const float*)d_in[16];
    const float* bo      = (const float*)d_in[17];
    float* out = (float*)d_out;

    cudaFuncSetAttribute(conv_mma_kernel,
                         cudaFuncAttributeMaxDynamicSharedMemorySize, CONV_SMEM);

    void* ys_ptr = nullptr;
    cudaGetSymbolAddress(&ys_ptr, g_ys);
    cudaMemsetAsync(ys_ptr, 0, L * H * sizeof(float));

    precompute_kernel<<<1, 1024>>>(Lre, Lim, logstep);

    dim3 pgrid(L / 32, 2);                    // 256 blocks
    proj_kernel<<<pgrid, 256>>>(x, Wb, bb, Wl, bl);

    dim3 wgrid(KTOT / 32, EPH / 32);          // (128, 32)
    wtrans_kernel<<<wgrid, 256>>>(cw);

    dim3 cgrid(L / GM, EPH / GN);             // (32, 8) = 256 CTAs
    conv_mma_kernel<<<cgrid, 256, CONV_SMEM>>>(cb);

    scan_p1_kernel<<<(CHUNKS * NCH) / 256, 256>>>(B);
    scan_p2_kernel<<<1, 1024>>>();
    scan_p3_kernel<<<(CHUNKS * NCH) / 256, 256>>>(B, C);

    final_kernel<<<L / 8, 256>>>(x, Wg, bg, Wd, bd, Wo, bo, out);
}

// round 14
// speedup vs baseline: 1.1731x; 1.0072x over previous
#include <cuda_runtime.h>
#include <cuda_fp16.h>
#include <math.h>
#include <stdint.h>

// Problem constants
#define L 4096
#define H 32
#define EP 32
#define EPH 1024
#define KTAP 4
#define NCH 1024
#define CHUNKS 64
#define CHUNK_LEN 64
#define KTOT 4096          // effective GEMM K = KTAP * EPH

// ---------------- scratch (device globals) ----------------
__device__ __half g_Apad[(L + 3) * EPH];     // padded tap-shift A, fp16
__device__ __half g_WT  [EPH * KTOT];        // conv weights transposed [o][kk], fp16
__device__ float  g_Lam  [L * EPH];
__device__ float  g_Bact [L * EPH];
__device__ float  g_ys   [L * H];
__device__ float4 g_agg  [CHUNKS * NCH];
__device__ float2 g_carry[CHUNKS * NCH];
__device__ float4 g_cA   [NCH];   // (a0x, cos(a0y), sin(a0y), 0)
__device__ float2 g_cB   [NCH];   // Bc complex

__device__ __forceinline__ float siluf(float v) {
    return v / (1.0f + expf(-v));
}

__device__ __forceinline__ uint32_t smem_u32(const void* p) {
    uint32_t a;
    asm("{ .reg .u64 t; cvta.to.shared.u64 t, %1; cvt.u32.u64 %0, t; }" : "=r"(a) : "l"(p));
    return a;
}

#define CP_ASYNC16(dst, src) \
    asm volatile("cp.async.cg.shared.global [%0], [%1], 16;" :: "r"(dst), "l"(src))
#define CP_COMMIT() asm volatile("cp.async.commit_group;" ::: "memory")
#define CP_WAIT2()  asm volatile("cp.async.wait_group 2;" ::: "memory")

__device__ __forceinline__ void ldm_x4(uint32_t* r, uint32_t addr) {
    asm volatile("ldmatrix.sync.aligned.m8n8.x4.shared.b16 {%0,%1,%2,%3}, [%4];"
                 : "=r"(r[0]), "=r"(r[1]), "=r"(r[2]), "=r"(r[3]) : "r"(addr));
}

__device__ __forceinline__ void mma16816(float* c, const uint32_t* a,
                                         uint32_t b0, uint32_t b1) {
    asm volatile(
        "mma.sync.aligned.m16n8k16.row.col.f32.f16.f16.f32 "
        "{%0,%1,%2,%3}, {%4,%5,%6,%7}, {%8,%9}, {%0,%1,%2,%3};"
        : "+f"(c[0]), "+f"(c[1]), "+f"(c[2]), "+f"(c[3])
        : "r"(a[0]), "r"(a[1]), "r"(a[2]), "r"(a[3]), "r"(b0), "r"(b1));
}

// fast elementwise recompute: A = log(1+exp(A0+lam)) (complex), Bu = Bc*Bt*ba
__device__ __forceinline__ void compute_ABu(float lam, float ba, float br, float bi,
                                            float a0x, float cz, float sz,
                                            float bcx, float bcy,
                                            float& Ar, float& Ai,
                                            float& bur, float& bui) {
    float e  = __expf(a0x + lam);
    float wr = fmaf(e, cz, 1.0f);
    float wi = e * sz;
    Ar = 0.5f * __logf(fmaf(wr, wr, wi * wi));
    float r  = __fdividef(wi, wr);
    float r2 = r * r;
    Ai = r * fmaf(r2, fmaf(r2, fmaf(r2, fmaf(r2, fmaf(r2,
            -0.0909090909f, 0.1111111111f), -0.1428571429f),
             0.2f), -0.3333333333f), 1.0f);
    bur = (bcx * br - bcy * bi) * ba;
    bui = (bcx * bi + bcy * br) * ba;
}

// ---------------- K0: precompute constants + zero pad rows -----------------------
__global__ void precompute_kernel(const float* __restrict__ Lre,
                                  const float* __restrict__ Lim,
                                  const float* __restrict__ logstep) {
    int c = threadIdx.x;
    int h = c >> 5;
    float st = expf(logstep[h]);
    float lr = Lre[c], li = Lim[c];
    float zr = lr * st, zi = li * st;
    float e  = expf(zr);
    float a0r = e * cosf(zi);
    float a0i = e * sinf(zi);
    float nr = a0r - 1.0f, ni = a0i;
    float inv = 1.0f / (lr * lr + li * li);
    g_cA[c] = make_float4(a0r, cosf(a0i), sinf(a0i), 0.0f);
    g_cB[c] = make_float2((nr * lr + ni * li) * inv, (ni * lr - nr * li) * inv);

    __half z = __float2half(0.0f);
    g_Apad[0 * EPH + c] = z;
    g_Apad[(L + 1) * EPH + c] = z;
    g_Apad[(L + 2) * EPH + c] = z;
}

// ---------------- K1: B_proj (fp16 into padded buf) ; Lam = silu(x@Wl) -----------
// grid (L/32, 4): o-quarters split across blockIdx.y
__global__ __launch_bounds__(256) void proj_kernel(const float* __restrict__ x,
                                                   const float* __restrict__ Wb,
                                                   const float* __restrict__ bb,
                                                   const float* __restrict__ Wl,
                                                   const float* __restrict__ bl) {
    __shared__ float xsm[32][33];
    int lb = blockIdx.x * 32;
    int o  = blockIdx.y * 256 + threadIdx.x;
    int t  = threadIdx.x;
    for (int i = t; i < 32 * 32; i += 256) {
        int r = i >> 5, h = i & 31;
        xsm[r][h] = x[(lb + r) * H + h];
    }
    __syncthreads();

    {
        float wcol[32];
        #pragma unroll
        for (int h = 0; h < 32; h++) wcol[h] = Wb[h * EPH + o];
        float bv = bb[o];
        for (int r = 0; r < 32; r++) {
            float acc = bv;
            #pragma unroll
            for (int h = 0; h < 32; h++) acc += xsm[r][h] * wcol[h];
            g_Apad[(lb + r + 1) * EPH + o] = __float2half(acc);
        }
    }
    {
        float wcol[32];
        #pragma unroll
        for (int h = 0; h < 32; h++) wcol[h] = Wl[h * EPH + o];
        float bv = bl[o];
        for (int r = 0; r < 32; r++) {
            float acc = bv;
            #pragma unroll
            for (int h = 0; h < 32; h++) acc += xsm[r][h] * wcol[h];
            g_Lam[(lb + r) * EPH + o] = siluf(acc);
        }
    }
}

// ---------------- K1b: transpose conv weights to [o][kk] fp16 --------------------
__global__ __launch_bounds__(256) void wtrans_kernel(const float* __restrict__ cw) {
    __shared__ float tile[32][33];
    int k0 = blockIdx.x * 32;
    int o0 = blockIdx.y * 32;
    int t = threadIdx.x;
    int r = t >> 5, c = t & 31;
    #pragma unroll
    for (int rr = r; rr < 32; rr += 8)
        tile[rr][c] = cw[(size_t)(k0 + rr) * EPH + o0 + c];
    __syncthreads();
    #pragma unroll
    for (int rr = r; rr < 32; rr += 8) {
        float v = tile[c][rr];
        size_t idx = (size_t)(o0 + rr) * KTOT + k0 + c;
        g_WT[idx] = __float2half(v);
    }
}

// ---------------- K2: conv GEMM via mma.sync fp16 (single product) ---------------
// R8 winner config exactly: 128x128 tile, 8 warps (4m x 2n), GK=32,
// ROWB=80, 4-stage cp.async (wait_group 2), 2 CTAs/SM.
#define GM 128
#define GN 128
#define GK 32
#define NCHUNK (KTOT / GK)        // 128
#define ROWB 80
#define TILE_B (128 * ROWB)
#define BUF_B (2 * TILE_B)
#define STAGES 4
#define CONV_SMEM (STAGES * BUF_B)  // 81920

__global__ __launch_bounds__(256, 2)
void conv_mma_kernel(const float* __restrict__ cb) {
    extern __shared__ char smem[];
    uint32_t sbase = smem_u32(smem);
    int t = threadIdx.x;
    int lane = t & 31;
    int wid = t >> 5;
    int warp_m = wid & 3;
    int warp_n = wid >> 2;
    int lb = blockIdx.x * GM;
    int nb = blockIdx.y * GN;

    float acc[2][8][4];
    #pragma unroll
    for (int i = 0; i < 2; i++)
        #pragma unroll
        for (int j = 0; j < 8; j++)
            #pragma unroll
            for (int k = 0; k < 4; k++) acc[i][j][k] = 0.0f;

    int lrow = t >> 1;
    int lhalf = t & 1;
    uint32_t dpos = lrow * ROWB + lhalf * 32;

    auto issue = [&](int kc) {
        uint32_t base = sbase + (kc & 3) * BUF_B;
        int kg = kc * GK;
        int tap = kg >> 10;
        int i0 = kg & 1023;
        {
            size_t go = (size_t)(lb + lrow + tap) * EPH + i0 + lhalf * 16;
            const char* sp = (const char*)(g_Apad + go);
            CP_ASYNC16(base + dpos,      sp);
            CP_ASYNC16(base + dpos + 16, sp + 16);
        }
        {
            size_t go = (size_t)(nb + lrow) * KTOT + kg + lhalf * 16;
            const char* sw = (const char*)(g_WT + go);
            CP_ASYNC16(base + TILE_B + dpos,      sw);
            CP_ASYNC16(base + TILE_B + dpos + 16, sw + 16);
        }
    };

    int lr8 = lane & 7;
    int lsel = lane >> 3;
    int lmn = (lsel & 1) * 8 + lr8;
    int lk8 = (lsel >> 1) * 8;

    issue(0); CP_COMMIT();
    issue(1); CP_COMMIT();
    issue(2); CP_COMMIT();

    for (int kc = 0; kc < NCHUNK; kc++) {
        CP_WAIT2();
        __syncthreads();
        if (kc + 3 < NCHUNK) issue(kc + 3);
        CP_COMMIT();

        uint32_t base = sbase + (kc & 3) * BUF_B;
        uint32_t Ah = base;
        uint32_t Wt = base + TILE_B;

        #pragma unroll
        for (int ks = 0; ks < 2; ks++) {
            int kbyte = (ks * 16 + lk8) * 2;
            uint32_t ah[2][4];
            #pragma unroll
            for (int im = 0; im < 2; im++) {
                uint32_t ro = (warp_m * 32 + im * 16 + lmn) * ROWB + kbyte;
                ldm_x4(ah[im], Ah + ro);
            }
            uint32_t w[4][4];
            #pragma unroll
            for (int in4 = 0; in4 < 4; in4++) {
                uint32_t ro = (warp_n * 64 + in4 * 16 + lmn) * ROWB + kbyte;
                ldm_x4(w[in4], Wt + ro);
            }
            #pragma unroll
            for (int in4 = 0; in4 < 4; in4++)
                #pragma unroll
                for (int im = 0; im < 2; im++) {
                    mma16816(acc[im][in4 * 2 + 0], ah[im], w[in4][0], w[in4][2]);
                    mma16816(acc[im][in4 * 2 + 1], ah[im], w[in4][1], w[in4][3]);
                }
        }
    }

    int gid = lane >> 2;
    int tig = lane & 3;
    #pragma unroll
    for (int im = 0; im < 2; im++) {
        int r0 = lb + warp_m * 32 + im * 16 + gid;
        #pragma unroll
        for (int j = 0; j < 8; j++) {
            int col = nb + warp_n * 64 + j * 8 + tig * 2;
            float b0 = cb[col], b1 = cb[col + 1];
            g_Bact[(size_t)r0 * EPH + col]           = siluf(acc[im][j][0] + b0);
            g_Bact[(size_t)r0 * EPH + col + 1]       = siluf(acc[im][j][1] + b1);
            g_Bact[(size_t)(r0 + 8) * EPH + col]     = siluf(acc[im][j][2] + b0);
            g_Bact[(size_t)(r0 + 8) * EPH + col + 1] = siluf(acc[im][j][3] + b1);
        }
    }
}

// ---------------- K3: scan pass 1 (recompute A/Bu inline) + zero ys --------------
__global__ __launch_bounds__(256) void scan_p1_kernel(const float* __restrict__ B) {
    int t = blockIdx.x * blockDim.x + threadIdx.x;   // CHUNKS*NCH = 65536
    // zero ys (131072 floats; 2 per thread) -- consumed only by scan_p3 later
    g_ys[2 * t]     = 0.0f;
    g_ys[2 * t + 1] = 0.0f;

    int c = t & (NCH - 1);
    int ch = t >> 10;
    int base = ch * CHUNK_LEN;
    int ep = c & 31;

    float4 cA = g_cA[c];
    float2 cB = g_cB[c];

    float Pr = 1.0f, Pi = 0.0f, sr = 0.0f, si = 0.0f;
    for (int i = 0; i < CHUNK_LEN; i++) {
        int l = base + i;
        int idx = l * NCH + c;
        float lam = g_Lam[idx];
        float ba  = g_Bact[idx];
        float br = B[l * 64 + ep * 2 + 0];
        float bi = B[l * 64 + ep * 2 + 1];
        float Ar, Ai, bur, bui;
        compute_ABu(lam, ba, br, bi, cA.x, cA.y, cA.z, cB.x, cB.y, Ar, Ai, bur, bui);

        float nsr = Ar * sr - Ai * si + bur;
        float nsi = Ar * si + Ai * sr + bui;
        sr = nsr; si = nsi;
        float npr = Ar * Pr - Ai * Pi;
        float npi = Ar * Pi + Ai * Pr;
        Pr = npr; Pi = npi;
    }
    g_agg[ch * NCH + c] = make_float4(Pr, Pi, sr, si);
}

// ---------------- K4: scan pass 2 (serial over chunks) ---------------------------
__global__ __launch_bounds__(1024) void scan_p2_kernel() {
    int c = threadIdx.x;
    float cr = 0.0f, ci = 0.0f;
    #pragma unroll
    for (int ch = 0; ch < CHUNKS; ch++) {
        g_carry[ch * NCH + c] = make_float2(cr, ci);
        float4 g = g_agg[ch * NCH + c];
        float nr = g.x * cr - g.y * ci + g.z;
        float ni = g.x * ci + g.y * cr + g.w;
        cr = nr; ci = ni;
    }
}

// ---------------- K5: scan pass 3 (recompute A/Bu, fused ys via atomics) ---------
__global__ __launch_bounds__(256) void scan_p3_kernel(const float* __restrict__ B,
                                                      const float* __restrict__ C) {
    int t = blockIdx.x * blockDim.x + threadIdx.x;
    int c = t & (NCH - 1);
    int ch = t >> 10;
    int base = ch * CHUNK_LEN;
    int ep = c & 31;
    int p = c >> 5;
    int j = c & 31;

    float4 cA = g_cA[c];
    float2 cB = g_cB[c];

    float2 st = g_carry[ch * NCH + c];
    float xr = st.x, xi = st.y;
    for (int i = 0; i < CHUNK_LEN; i++) {
        int l = base + i;
        int idx = l * NCH + c;
        float lam = g_Lam[idx];
        float ba  = g_Bact[idx];
        float br = B[l * 64 + ep * 2 + 0];
        float bi = B[l * 64 + ep * 2 + 1];
        float Ar, Ai, bur, bui;
        compute_ABu(lam, ba, br, bi, cA.x, cA.y, cA.z, cB.x, cB.y, Ar, Ai, bur, bui);

        float nxr = Ar * xr - Ai * xi + bur;
        float nxi = Ar * xi + Ai * xr + bui;
        xr = nxr; xi = nxi;

        float cr = C[l * 64 + p * 2 + 0];
        float ci = C[l * 64 + p * 2 + 1];
        atomicAdd(&g_ys[l * H + j], cr * xr - ci * xi);
    }
}

// ---------------- K8: gating + output projection ---------------------------------
__global__ __launch_bounds__(256) void final_kernel(const float* __restrict__ x,
                                                    const float* __restrict__ Wg,
                                                    const float* __restrict__ bg,
                                                    const float* __restrict__ Wd,
                                                    const float* __restrict__ bd,
                                                    const float* __restrict__ Wo,
                                                    const float* __restrict__ bo,
                                                    float* __restrict__ out) {
    __shared__ float sWg[H * H], sWo[H * H];
    __shared__ float sWd[H], sbg[H], sbo[H];
    __shared__ float sx[8][H], sht[8][H];
    int t = threadIdx.x;
    for (int i = t; i < H * H; i += 256) { sWg[i] = Wg[i]; sWo[i] = Wo[i]; }
    if (t < H) { sWd[t] = Wd[t]; sbg[t] = bg[t]; sbo[t] = bo[t]; }
    int lane = t & 31;
    int w = t >> 5;
    int l = blockIdx.x * 8 + w;
    sx[w][lane] = x[l * H + lane];
    __syncthreads();

    float xg = 0.0f, xd = 0.0f;
    #pragma unroll
    for (int h = 0; h < H; h++) {
        float xv = sx[w][h];
        xg += xv * sWg[h * H + lane];
        xd += xv * sWd[h];
    }
    float gt = siluf(xg + sbg[lane]);
    float d  = log1pf(expf(xd + bd[0]));
    float ysv = g_ys[l * H + lane];
    float xv  = sx[w][lane];
    float ht = (1.0f - gt) * (ysv + d * xv) + gt * xv;
    sht[w][lane] = ht;
    __syncwarp();

    float o = 0.0f;
    #pragma unroll
    for (int h = 0; h < H; h++) o += sht[w][h] * sWo[h * H + lane];
    out[l * H + lane] = o + sbo[lane];
}

// ---------------- launcher -------------------------------------------------------
extern "C" void kernel_launch(void* const* d_in, const int* in_sizes, int n_in,
                              void* d_out, int out_size) {
    const float* x       = (const float*)d_in[0];
    const float* Lre     = (const float*)d_in[1];
    const float* Lim     = (const float*)d_in[2];
    const float* B       = (const float*)d_in[3];
    const float* C       = (const float*)d_in[4];
    const float* logstep = (const float*)d_in[5];
    const float* Wb      = (const float*)d_in[6];
    const float* bb      = (const float*)d_in[7];
    const float* Wl      = (const float*)d_in[8];
    const float* bl      = (const float*)d_in[9];
    const float* cw      = (const float*)d_in[10];
    const float* cb      = (const float*)d_in[11];
    const float* Wg      = (const float*)d_in[12];
    const float* bg      = (const float*)d_in[13];
    const float* Wd      = (const float*)d_in[14];
    const float* bd      = (const float*)d_in[15];
    const float* Wo      = (const float*)d_in[16];
    const float* bo      = (const float*)d_in[17];
    float* out = (float*)d_out;

    cudaFuncSetAttribute(conv_mma_kernel,
                         cudaFuncAttributeMaxDynamicSharedMemorySize, CONV_SMEM);

    precompute_kernel<<<1, 1024>>>(Lre, Lim, logstep);

    dim3 pgrid(L / 32, 4);                    // 512 blocks
    proj_kernel<<<pgrid, 256>>>(x, Wb, bb, Wl, bl);

    dim3 wgrid(KTOT / 32, EPH / 32);          // (128, 32)
    wtrans_kernel<<<wgrid, 256>>>(cw);

    dim3 cgrid(L / GM, EPH / GN);             // (32, 8) = 256 CTAs
    conv_mma_kernel<<<cgrid, 256, CONV_SMEM>>>(cb);

    scan_p1_kernel<<<(CHUNKS * NCH) / 256, 256>>>(B);
    scan_p2_kernel<<<1, 1024>>>();
    scan_p3_kernel<<<(CHUNKS * NCH) / 256, 256>>>(B, C);

    final_kernel<<<L / 8, 256>>>(x, Wg, bg, Wd, bd, Wo, bo, out);
}

// round 15
// speedup vs baseline: 1.1854x; 1.0105x over previous
#include <cuda_runtime.h>
#include <cuda_fp16.h>
#include <math.h>
#include <stdint.h>

// Problem constants
#define L 4096
#define H 32
#define EP 32
#define EPH 1024
#define KTAP 4
#define NCH 1024
#define CHUNKS 64
#define CHUNK_LEN 64
#define KTOT 4096          // effective GEMM K = KTAP * EPH

// ---------------- scratch (device globals) ----------------
__device__ __half g_Apad[(L + 3) * EPH];     // padded tap-shift A, fp16
__device__ __half g_WT  [EPH * KTOT];        // conv weights transposed [o][kk], fp16
__device__ float  g_Lam  [L * EPH];
__device__ float  g_Bact [L * EPH];
__device__ float  g_ys   [L * H];
__device__ float4 g_agg  [CHUNKS * NCH];
__device__ float2 g_carry[CHUNKS * NCH];
__device__ float4 g_cA   [NCH];   // (a0x, cos(a0y), sin(a0y), 0)
__device__ float2 g_cB   [NCH];   // Bc complex

__device__ __forceinline__ float siluf(float v) {
    return v / (1.0f + expf(-v));
}

__device__ __forceinline__ uint32_t smem_u32(const void* p) {
    uint32_t a;
    asm("{ .reg .u64 t; cvta.to.shared.u64 t, %1; cvt.u32.u64 %0, t; }" : "=r"(a) : "l"(p));
    return a;
}

#define CP_ASYNC16(dst, src) \
    asm volatile("cp.async.cg.shared.global [%0], [%1], 16;" :: "r"(dst), "l"(src))
#define CP_COMMIT() asm volatile("cp.async.commit_group;" ::: "memory")
#define CP_WAIT2()  asm volatile("cp.async.wait_group 2;" ::: "memory")

__device__ __forceinline__ void ldm_x4(uint32_t* r, uint32_t addr) {
    asm volatile("ldmatrix.sync.aligned.m8n8.x4.shared.b16 {%0,%1,%2,%3}, [%4];"
                 : "=r"(r[0]), "=r"(r[1]), "=r"(r[2]), "=r"(r[3]) : "r"(addr));
}

__device__ __forceinline__ void mma16816(float* c, const uint32_t* a,
                                         uint32_t b0, uint32_t b1) {
    asm volatile(
        "mma.sync.aligned.m16n8k16.row.col.f32.f16.f16.f32 "
        "{%0,%1,%2,%3}, {%4,%5,%6,%7}, {%8,%9}, {%0,%1,%2,%3};"
        : "+f"(c[0]), "+f"(c[1]), "+f"(c[2]), "+f"(c[3])
        : "r"(a[0]), "r"(a[1]), "r"(a[2]), "r"(a[3]), "r"(b0), "r"(b1));
}

// fast elementwise recompute: A = log(1+exp(A0+lam)) (complex), Bu = Bc*Bt*ba
__device__ __forceinline__ void compute_ABu(float lam, float ba, float br, float bi,
                                            float a0x, float cz, float sz,
                                            float bcx, float bcy,
                                            float& Ar, float& Ai,
                                            float& bur, float& bui) {
    float e  = __expf(a0x + lam);
    float wr = fmaf(e, cz, 1.0f);
    float wi = e * sz;
    Ar = 0.5f * __logf(fmaf(wr, wr, wi * wi));
    float r  = __fdividef(wi, wr);
    float r2 = r * r;
    Ai = r * fmaf(r2, fmaf(r2, fmaf(r2, fmaf(r2, fmaf(r2,
            -0.0909090909f, 0.1111111111f), -0.1428571429f),
             0.2f), -0.3333333333f), 1.0f);
    bur = (bcx * br - bcy * bi) * ba;
    bui = (bcx * bi + bcy * br) * ba;
}

// ---------------- K0: precompute constants + zero pad rows -----------------------
__global__ void precompute_kernel(const float* __restrict__ Lre,
                                  const float* __restrict__ Lim,
                                  const float* __restrict__ logstep) {
    int c = threadIdx.x;
    int h = c >> 5;
    float st = expf(logstep[h]);
    float lr = Lre[c], li = Lim[c];
    float zr = lr * st, zi = li * st;
    float e  = expf(zr);
    float a0r = e * cosf(zi);
    float a0i = e * sinf(zi);
    float nr = a0r - 1.0f, ni = a0i;
    float inv = 1.0f / (lr * lr + li * li);
    g_cA[c] = make_float4(a0r, cosf(a0i), sinf(a0i), 0.0f);
    g_cB[c] = make_float2((nr * lr + ni * li) * inv, (ni * lr - nr * li) * inv);

    __half z = __float2half(0.0f);
    g_Apad[0 * EPH + c] = z;
    g_Apad[(L + 1) * EPH + c] = z;
    g_Apad[(L + 2) * EPH + c] = z;
}

// ---------------- K1: B_proj (fp16 into padded buf) ; Lam = silu(x@Wl) -----------
// grid (L/32, 4): o-quarters split across blockIdx.y
__global__ __launch_bounds__(256) void proj_kernel(const float* __restrict__ x,
                                                   const float* __restrict__ Wb,
                                                   const float* __restrict__ bb,
                                                   const float* __restrict__ Wl,
                                                   const float* __restrict__ bl) {
    __shared__ float xsm[32][33];
    int lb = blockIdx.x * 32;
    int o  = blockIdx.y * 256 + threadIdx.x;
    int t  = threadIdx.x;
    for (int i = t; i < 32 * 32; i += 256) {
        int r = i >> 5, h = i & 31;
        xsm[r][h] = x[(lb + r) * H + h];
    }
    __syncthreads();

    {
        float wcol[32];
        #pragma unroll
        for (int h = 0; h < 32; h++) wcol[h] = Wb[h * EPH + o];
        float bv = bb[o];
        for (int r = 0; r < 32; r++) {
            float acc = bv;
            #pragma unroll
            for (int h = 0; h < 32; h++) acc += xsm[r][h] * wcol[h];
            g_Apad[(lb + r + 1) * EPH + o] = __float2half(acc);
        }
    }
    {
        float wcol[32];
        #pragma unroll
        for (int h = 0; h < 32; h++) wcol[h] = Wl[h * EPH + o];
        float bv = bl[o];
        for (int r = 0; r < 32; r++) {
            float acc = bv;
            #pragma unroll
            for (int h = 0; h < 32; h++) acc += xsm[r][h] * wcol[h];
            g_Lam[(lb + r) * EPH + o] = siluf(acc);
        }
    }
}

// ---------------- K1b: transpose conv weights to [o][kk] fp16 --------------------
__global__ __launch_bounds__(256) void wtrans_kernel(const float* __restrict__ cw) {
    __shared__ float tile[32][33];
    int k0 = blockIdx.x * 32;
    int o0 = blockIdx.y * 32;
    int t = threadIdx.x;
    int r = t >> 5, c = t & 31;
    #pragma unroll
    for (int rr = r; rr < 32; rr += 8)
        tile[rr][c] = cw[(size_t)(k0 + rr) * EPH + o0 + c];
    __syncthreads();
    #pragma unroll
    for (int rr = r; rr < 32; rr += 8) {
        float v = tile[c][rr];
        size_t idx = (size_t)(o0 + rr) * KTOT + k0 + c;
        g_WT[idx] = __float2half(v);
    }
}

// ---------------- K2: conv GEMM via mma.sync fp16 (single product) ---------------
// R8 winner config exactly: 128x128 tile, 8 warps (4m x 2n), GK=32,
// ROWB=80, 4-stage cp.async (wait_group 2), 2 CTAs/SM.
#define GM 128
#define GN 128
#define GK 32
#define NCHUNK (KTOT / GK)        // 128
#define ROWB 80
#define TILE_B (128 * ROWB)
#define BUF_B (2 * TILE_B)
#define STAGES 4
#define CONV_SMEM (STAGES * BUF_B)  // 81920

__global__ __launch_bounds__(256, 2)
void conv_mma_kernel(const float* __restrict__ cb) {
    extern __shared__ char smem[];
    uint32_t sbase = smem_u32(smem);
    int t = threadIdx.x;
    int lane = t & 31;
    int wid = t >> 5;
    int warp_m = wid & 3;
    int warp_n = wid >> 2;
    int lb = blockIdx.x * GM;
    int nb = blockIdx.y * GN;

    float acc[2][8][4];
    #pragma unroll
    for (int i = 0; i < 2; i++)
        #pragma unroll
        for (int j = 0; j < 8; j++)
            #pragma unroll
            for (int k = 0; k < 4; k++) acc[i][j][k] = 0.0f;

    int lrow = t >> 1;
    int lhalf = t & 1;
    uint32_t dpos = lrow * ROWB + lhalf * 32;

    auto issue = [&](int kc) {
        uint32_t base = sbase + (kc & 3) * BUF_B;
        int kg = kc * GK;
        int tap = kg >> 10;
        int i0 = kg & 1023;
        {
            size_t go = (size_t)(lb + lrow + tap) * EPH + i0 + lhalf * 16;
            const char* sp = (const char*)(g_Apad + go);
            CP_ASYNC16(base + dpos,      sp);
            CP_ASYNC16(base + dpos + 16, sp + 16);
        }
        {
            size_t go = (size_t)(nb + lrow) * KTOT + kg + lhalf * 16;
            const char* sw = (const char*)(g_WT + go);
            CP_ASYNC16(base + TILE_B + dpos,      sw);
            CP_ASYNC16(base + TILE_B + dpos + 16, sw + 16);
        }
    };

    int lr8 = lane & 7;
    int lsel = lane >> 3;
    int lmn = (lsel & 1) * 8 + lr8;
    int lk8 = (lsel >> 1) * 8;

    issue(0); CP_COMMIT();
    issue(1); CP_COMMIT();
    issue(2); CP_COMMIT();

    for (int kc = 0; kc < NCHUNK; kc++) {
        CP_WAIT2();
        __syncthreads();
        if (kc + 3 < NCHUNK) issue(kc + 3);
        CP_COMMIT();

        uint32_t base = sbase + (kc & 3) * BUF_B;
        uint32_t Ah = base;
        uint32_t Wt = base + TILE_B;

        #pragma unroll
        for (int ks = 0; ks < 2; ks++) {
            int kbyte = (ks * 16 + lk8) * 2;
            uint32_t ah[2][4];
            #pragma unroll
            for (int im = 0; im < 2; im++) {
                uint32_t ro = (warp_m * 32 + im * 16 + lmn) * ROWB + kbyte;
                ldm_x4(ah[im], Ah + ro);
            }
            uint32_t w[4][4];
            #pragma unroll
            for (int in4 = 0; in4 < 4; in4++) {
                uint32_t ro = (warp_n * 64 + in4 * 16 + lmn) * ROWB + kbyte;
                ldm_x4(w[in4], Wt + ro);
            }
            #pragma unroll
            for (int in4 = 0; in4 < 4; in4++)
                #pragma unroll
                for (int im = 0; im < 2; im++) {
                    mma16816(acc[im][in4 * 2 + 0], ah[im], w[in4][0], w[in4][2]);
                    mma16816(acc[im][in4 * 2 + 1], ah[im], w[in4][1], w[in4][3]);
                }
        }
    }

    // epilogue: bias + silu, float2 stores
    int gid = lane >> 2;
    int tig = lane & 3;
    #pragma unroll
    for (int im = 0; im < 2; im++) {
        int r0 = lb + warp_m * 32 + im * 16 + gid;
        #pragma unroll
        for (int j = 0; j < 8; j++) {
            int col = nb + warp_n * 64 + j * 8 + tig * 2;
            float b0 = cb[col], b1 = cb[col + 1];
            float2 v0 = make_float2(siluf(acc[im][j][0] + b0), siluf(acc[im][j][1] + b1));
            float2 v1 = make_float2(siluf(acc[im][j][2] + b0), siluf(acc[im][j][3] + b1));
            *(float2*)&g_Bact[(size_t)r0 * EPH + col]       = v0;
            *(float2*)&g_Bact[(size_t)(r0 + 8) * EPH + col] = v1;
        }
    }
}

// ---------------- K3: scan pass 1 (recompute A/Bu inline) + zero ys --------------
__global__ __launch_bounds__(256) void scan_p1_kernel(const float* __restrict__ B) {
    int t = blockIdx.x * blockDim.x + threadIdx.x;   // CHUNKS*NCH = 65536
    g_ys[2 * t]     = 0.0f;
    g_ys[2 * t + 1] = 0.0f;

    int c = t & (NCH - 1);
    int ch = t >> 10;
    int base = ch * CHUNK_LEN;
    int ep = c & 31;

    float4 cA = g_cA[c];
    float2 cB = g_cB[c];

    float Pr = 1.0f, Pi = 0.0f, sr = 0.0f, si = 0.0f;
    for (int i = 0; i < CHUNK_LEN; i++) {
        int l = base + i;
        int idx = l * NCH + c;
        float lam = g_Lam[idx];
        float ba  = g_Bact[idx];
        float br = B[l * 64 + ep * 2 + 0];
        float bi = B[l * 64 + ep * 2 + 1];
        float Ar, Ai, bur, bui;
        compute_ABu(lam, ba, br, bi, cA.x, cA.y, cA.z, cB.x, cB.y, Ar, Ai, bur, bui);

        float nsr = Ar * sr - Ai * si + bur;
        float nsi = Ar * si + Ai * sr + bui;
        sr = nsr; si = nsi;
        float npr = Ar * Pr - Ai * Pi;
        float npi = Ar * Pi + Ai * Pr;
        Pr = npr; Pi = npi;
    }
    g_agg[ch * NCH + c] = make_float4(Pr, Pi, sr, si);
}

// ---------------- K4: scan pass 2 (serial over chunks, MLP-prefetched) -----------
__global__ __launch_bounds__(1024) void scan_p2_kernel() {
    int c = threadIdx.x;
    float cr = 0.0f, ci = 0.0f;
    #pragma unroll
    for (int g0 = 0; g0 < CHUNKS; g0 += 8) {
        float4 g[8];
        #pragma unroll
        for (int k = 0; k < 8; k++)
            g[k] = g_agg[(g0 + k) * NCH + c];
        #pragma unroll
        for (int k = 0; k < 8; k++) {
            g_carry[(g0 + k) * NCH + c] = make_float2(cr, ci);
            float nr = g[k].x * cr - g[k].y * ci + g[k].z;
            float ni = g[k].x * ci + g[k].y * cr + g[k].w;
            cr = nr; ci = ni;
        }
    }
}

// ---------------- K5: scan pass 3 (recompute A/Bu, fused ys via atomics) ---------
__global__ __launch_bounds__(256) void scan_p3_kernel(const float* __restrict__ B,
                                                      const float* __restrict__ C) {
    int t = blockIdx.x * blockDim.x + threadIdx.x;
    int c = t & (NCH - 1);
    int ch = t >> 10;
    int base = ch * CHUNK_LEN;
    int ep = c & 31;
    int p = c >> 5;
    int j = c & 31;

    float4 cA = g_cA[c];
    float2 cB = g_cB[c];

    float2 st = g_carry[ch * NCH + c];
    float xr = st.x, xi = st.y;
    for (int i = 0; i < CHUNK_LEN; i++) {
        int l = base + i;
        int idx = l * NCH + c;
        float lam = g_Lam[idx];
        float ba  = g_Bact[idx];
        float br = B[l * 64 + ep * 2 + 0];
        float bi = B[l * 64 + ep * 2 + 1];
        float Ar, Ai, bur, bui;
        compute_ABu(lam, ba, br, bi, cA.x, cA.y, cA.z, cB.x, cB.y, Ar, Ai, bur, bui);

        float nxr = Ar * xr - Ai * xi + bur;
        float nxi = Ar * xi + Ai * xr + bui;
        xr = nxr; xi = nxi;

        float cr = C[l * 64 + p * 2 + 0];
        float ci = C[l * 64 + p * 2 + 1];
        atomicAdd(&g_ys[l * H + j], cr * xr - ci * xi);
    }
}

// ---------------- K8: gating + output projection ---------------------------------
__global__ __launch_bounds__(256) void final_kernel(const float* __restrict__ x,
                                                    const float* __restrict__ Wg,
                                                    const float* __restrict__ bg,
                                                    const float* __restrict__ Wd,
                                                    const float* __restrict__ bd,
                                                    const float* __restrict__ Wo,
                                                    const float* __restrict__ bo,
                                                    float* __restrict__ out) {
    __shared__ float sWg[H * H], sWo[H * H];
    __shared__ float sWd[H], sbg[H], sbo[H];
    __shared__ float sx[8][H], sht[8][H];
    int t = threadIdx.x;
    for (int i = t; i < H * H; i += 256) { sWg[i] = Wg[i]; sWo[i] = Wo[i]; }
    if (t < H) { sWd[t] = Wd[t]; sbg[t] = bg[t]; sbo[t] = bo[t]; }
    int lane = t & 31;
    int w = t >> 5;
    int l = blockIdx.x * 8 + w;
    sx[w][lane] = x[l * H + lane];
    __syncthreads();

    float xg = 0.0f, xd = 0.0f;
    #pragma unroll
    for (int h = 0; h < H; h++) {
        float xv = sx[w][h];
        xg += xv * sWg[h * H + lane];
        xd += xv * sWd[h];
    }
    float gt = siluf(xg + sbg[lane]);
    float d  = log1pf(expf(xd + bd[0]));
    float ysv = g_ys[l * H + lane];
    float xv  = sx[w][lane];
    float ht = (1.0f - gt) * (ysv + d * xv) + gt * xv;
    sht[w][lane] = ht;
    __syncwarp();

    float o = 0.0f;
    #pragma unroll
    for (int h = 0; h < H; h++) o += sht[w][h] * sWo[h * H + lane];
    out[l * H + lane] = o + sbo[lane];
}

// ---------------- launcher -------------------------------------------------------
extern "C" void kernel_launch(void* const* d_in, const int* in_sizes, int n_in,
                              void* d_out, int out_size) {
    const float* x       = (const float*)d_in[0];
    const float* Lre     = (const float*)d_in[1];
    const float* Lim     = (const float*)d_in[2];
    const float* B       = (const float*)d_in[3];
    const float* C       = (const float*)d_in[4];
    const float* logstep = (const float*)d_in[5];
    const float* Wb      = (const float*)d_in[6];
    const float* bb      = (const float*)d_in[7];
    const float* Wl      = (const float*)d_in[8];
    const float* bl      = (const float*)d_in[9];
    const float* cw      = (const float*)d_in[10];
    const float* cb      = (const float*)d_in[11];
    const float* Wg      = (const float*)d_in[12];
    const float* bg      = (const float*)d_in[13];
    const float* Wd      = (const float*)d_in[14];
    const float* bd      = (const float*)d_in[15];
    const float* Wo      = (const float*)d_in[16];
    const float* bo      = (const float*)d_in[17];
    float* out = (float*)d_out;

    cudaFuncSetAttribute(conv_mma_kernel,
                         cudaFuncAttributeMaxDynamicSharedMemorySize, CONV_SMEM);

    precompute_kernel<<<1, 1024>>>(Lre, Lim, logstep);

    dim3 pgrid(L / 32, 4);                    // 512 blocks
    proj_kernel<<<pgrid, 256>>>(x, Wb, bb, Wl, bl);

    dim3 wgrid(KTOT / 32, EPH / 32);          // (128, 32)
    wtrans_kernel<<<wgrid, 256>>>(cw);

    dim3 cgrid(L / GM, EPH / GN);             // (32, 8) = 256 CTAs
    conv_mma_kernel<<<cgrid, 256, CONV_SMEM>>>(cb);

    scan_p1_kernel<<<(CHUNKS * NCH) / 256, 256>>>(B);
    scan_p2_kernel<<<1, 1024>>>();
    scan_p3_kernel<<<(CHUNKS * NCH) / 256, 256>>>(B, C);

    final_kernel<<<L / 8, 256>>>(x, Wg, bg, Wd, bd, Wo, bo, out);
}

// round 16
// speedup vs baseline: 1.2024x; 1.0143x over previous
#include <cuda_runtime.h>
#include <cuda_fp16.h>
#include <math.h>
#include <stdint.h>

// Problem constants
#define L 4096
#define H 32
#define EP 32
#define EPH 1024
#define KTAP 4
#define NCH 1024
#define CHUNKS 128
#define CHUNK_LEN 32
#define KTOT 4096          // effective GEMM K = KTAP * EPH

// ---------------- scratch (device globals) ----------------
__device__ __half g_Apad[(L + 3) * EPH];     // padded tap-shift A, fp16
__device__ __half g_WT  [EPH * KTOT];        // conv weights transposed [o][kk], fp16
__device__ float  g_Lam  [L * EPH];
__device__ float  g_Bact [L * EPH];
__device__ float  g_ys   [L * H];
__device__ float4 g_agg  [CHUNKS * NCH];
__device__ float2 g_carry[CHUNKS * NCH];
__device__ float4 g_cA   [NCH];   // (a0x, cos(a0y), sin(a0y), 0)
__device__ float2 g_cB   [NCH];   // Bc complex

__device__ __forceinline__ float siluf(float v) {
    return v / (1.0f + expf(-v));
}

__device__ __forceinline__ uint32_t smem_u32(const void* p) {
    uint32_t a;
    asm("{ .reg .u64 t; cvta.to.shared.u64 t, %1; cvt.u32.u64 %0, t; }" : "=r"(a) : "l"(p));
    return a;
}

#define CP_ASYNC16(dst, src) \
    asm volatile("cp.async.cg.shared.global [%0], [%1], 16;" :: "r"(dst), "l"(src))
#define CP_COMMIT() asm volatile("cp.async.commit_group;" ::: "memory")
#define CP_WAIT2()  asm volatile("cp.async.wait_group 2;" ::: "memory")

__device__ __forceinline__ void ldm_x4(uint32_t* r, uint32_t addr) {
    asm volatile("ldmatrix.sync.aligned.m8n8.x4.shared.b16 {%0,%1,%2,%3}, [%4];"
                 : "=r"(r[0]), "=r"(r[1]), "=r"(r[2]), "=r"(r[3]) : "r"(addr));
}

__device__ __forceinline__ void mma16816(float* c, const uint32_t* a,
                                         uint32_t b0, uint32_t b1) {
    asm volatile(
        "mma.sync.aligned.m16n8k16.row.col.f32.f16.f16.f32 "
        "{%0,%1,%2,%3}, {%4,%5,%6,%7}, {%8,%9}, {%0,%1,%2,%3};"
        : "+f"(c[0]), "+f"(c[1]), "+f"(c[2]), "+f"(c[3])
        : "r"(a[0]), "r"(a[1]), "r"(a[2]), "r"(a[3]), "r"(b0), "r"(b1));
}

// fast elementwise recompute: A = log(1+exp(A0+lam)) (complex), Bu = Bc*Bt*ba
__device__ __forceinline__ void compute_ABu(float lam, float ba, float br, float bi,
                                            float a0x, float cz, float sz,
                                            float bcx, float bcy,
                                            float& Ar, float& Ai,
                                            float& bur, float& bui) {
    float e  = __expf(a0x + lam);
    float wr = fmaf(e, cz, 1.0f);
    float wi = e * sz;
    Ar = 0.5f * __logf(fmaf(wr, wr, wi * wi));
    float r  = __fdividef(wi, wr);
    float r2 = r * r;
    Ai = r * fmaf(r2, fmaf(r2, fmaf(r2, fmaf(r2, fmaf(r2,
            -0.0909090909f, 0.1111111111f), -0.1428571429f),
             0.2f), -0.3333333333f), 1.0f);
    bur = (bcx * br - bcy * bi) * ba;
    bui = (bcx * bi + bcy * br) * ba;
}

// ---------------- K0: precompute constants + zero pad rows -----------------------
__global__ void precompute_kernel(const float* __restrict__ Lre,
                                  const float* __restrict__ Lim,
                                  const float* __restrict__ logstep) {
    int c = threadIdx.x;
    int h = c >> 5;
    float st = expf(logstep[h]);
    float lr = Lre[c], li = Lim[c];
    float zr = lr * st, zi = li * st;
    float e  = expf(zr);
    float a0r = e * cosf(zi);
    float a0i = e * sinf(zi);
    float nr = a0r - 1.0f, ni = a0i;
    float inv = 1.0f / (lr * lr + li * li);
    g_cA[c] = make_float4(a0r, cosf(a0i), sinf(a0i), 0.0f);
    g_cB[c] = make_float2((nr * lr + ni * li) * inv, (ni * lr - nr * li) * inv);

    __half z = __float2half(0.0f);
    g_Apad[0 * EPH + c] = z;
    g_Apad[(L + 1) * EPH + c] = z;
    g_Apad[(L + 2) * EPH + c] = z;
}

// ---------------- K1: B_proj (fp16 into padded buf) ; Lam = silu(x@Wl) -----------
// grid (L/32, 4): o-quarters split across blockIdx.y
__global__ __launch_bounds__(256) void proj_kernel(const float* __restrict__ x,
                                                   const float* __restrict__ Wb,
                                                   const float* __restrict__ bb,
                                                   const float* __restrict__ Wl,
                                                   const float* __restrict__ bl) {
    __shared__ float xsm[32][33];
    int lb = blockIdx.x * 32;
    int o  = blockIdx.y * 256 + threadIdx.x;
    int t  = threadIdx.x;
    for (int i = t; i < 32 * 32; i += 256) {
        int r = i >> 5, h = i & 31;
        xsm[r][h] = x[(lb + r) * H + h];
    }
    __syncthreads();

    {
        float wcol[32];
        #pragma unroll
        for (int h = 0; h < 32; h++) wcol[h] = Wb[h * EPH + o];
        float bv = bb[o];
        for (int r = 0; r < 32; r++) {
            float acc = bv;
            #pragma unroll
            for (int h = 0; h < 32; h++) acc += xsm[r][h] * wcol[h];
            g_Apad[(lb + r + 1) * EPH + o] = __float2half(acc);
        }
    }
    {
        float wcol[32];
        #pragma unroll
        for (int h = 0; h < 32; h++) wcol[h] = Wl[h * EPH + o];
        float bv = bl[o];
        for (int r = 0; r < 32; r++) {
            float acc = bv;
            #pragma unroll
            for (int h = 0; h < 32; h++) acc += xsm[r][h] * wcol[h];
            g_Lam[(lb + r) * EPH + o] = siluf(acc);
        }
    }
}

// ---------------- K1b: transpose conv weights to [o][kk] fp16 --------------------
__global__ __launch_bounds__(256) void wtrans_kernel(const float* __restrict__ cw) {
    __shared__ float tile[32][33];
    int k0 = blockIdx.x * 32;
    int o0 = blockIdx.y * 32;
    int t = threadIdx.x;
    int r = t >> 5, c = t & 31;
    #pragma unroll
    for (int rr = r; rr < 32; rr += 8)
        tile[rr][c] = cw[(size_t)(k0 + rr) * EPH + o0 + c];
    __syncthreads();
    #pragma unroll
    for (int rr = r; rr < 32; rr += 8) {
        float v = tile[c][rr];
        size_t idx = (size_t)(o0 + rr) * KTOT + k0 + c;
        g_WT[idx] = __float2half(v);
    }
}

// ---------------- K2: conv GEMM via mma.sync fp16 (single product) ---------------
// R8 winner config exactly: 128x128 tile, 8 warps (4m x 2n), GK=32,
// ROWB=80, 4-stage cp.async (wait_group 2), 2 CTAs/SM.
#define GM 128
#define GN 128
#define GK 32
#define NCHUNK (KTOT / GK)        // 128
#define ROWB 80
#define TILE_B (128 * ROWB)
#define BUF_B (2 * TILE_B)
#define STAGES 4
#define CONV_SMEM (STAGES * BUF_B)  // 81920

__global__ __launch_bounds__(256, 2)
void conv_mma_kernel(const float* __restrict__ cb) {
    extern __shared__ char smem[];
    uint32_t sbase = smem_u32(smem);
    int t = threadIdx.x;
    int lane = t & 31;
    int wid = t >> 5;
    int warp_m = wid & 3;
    int warp_n = wid >> 2;
    int lb = blockIdx.x * GM;
    int nb = blockIdx.y * GN;

    float acc[2][8][4];
    #pragma unroll
    for (int i = 0; i < 2; i++)
        #pragma unroll
        for (int j = 0; j < 8; j++)
            #pragma unroll
            for (int k = 0; k < 4; k++) acc[i][j][k] = 0.0f;

    int lrow = t >> 1;
    int lhalf = t & 1;
    uint32_t dpos = lrow * ROWB + lhalf * 32;

    auto issue = [&](int kc) {
        uint32_t base = sbase + (kc & 3) * BUF_B;
        int kg = kc * GK;
        int tap = kg >> 10;
        int i0 = kg & 1023;
        {
            size_t go = (size_t)(lb + lrow + tap) * EPH + i0 + lhalf * 16;
            const char* sp = (const char*)(g_Apad + go);
            CP_ASYNC16(base + dpos,      sp);
            CP_ASYNC16(base + dpos + 16, sp + 16);
        }
        {
            size_t go = (size_t)(nb + lrow) * KTOT + kg + lhalf * 16;
            const char* sw = (const char*)(g_WT + go);
            CP_ASYNC16(base + TILE_B + dpos,      sw);
            CP_ASYNC16(base + TILE_B + dpos + 16, sw + 16);
        }
    };

    int lr8 = lane & 7;
    int lsel = lane >> 3;
    int lmn = (lsel & 1) * 8 + lr8;
    int lk8 = (lsel >> 1) * 8;

    issue(0); CP_COMMIT();
    issue(1); CP_COMMIT();
    issue(2); CP_COMMIT();

    for (int kc = 0; kc < NCHUNK; kc++) {
        CP_WAIT2();
        __syncthreads();
        if (kc + 3 < NCHUNK) issue(kc + 3);
        CP_COMMIT();

        uint32_t base = sbase + (kc & 3) * BUF_B;
        uint32_t Ah = base;
        uint32_t Wt = base + TILE_B;

        #pragma unroll
        for (int ks = 0; ks < 2; ks++) {
            int kbyte = (ks * 16 + lk8) * 2;
            uint32_t ah[2][4];
            #pragma unroll
            for (int im = 0; im < 2; im++) {
                uint32_t ro = (warp_m * 32 + im * 16 + lmn) * ROWB + kbyte;
                ldm_x4(ah[im], Ah + ro);
            }
            uint32_t w[4][4];
            #pragma unroll
            for (int in4 = 0; in4 < 4; in4++) {
                uint32_t ro = (warp_n * 64 + in4 * 16 + lmn) * ROWB + kbyte;
                ldm_x4(w[in4], Wt + ro);
            }
            #pragma unroll
            for (int in4 = 0; in4 < 4; in4++)
                #pragma unroll
                for (int im = 0; im < 2; im++) {
                    mma16816(acc[im][in4 * 2 + 0], ah[im], w[in4][0], w[in4][2]);
                    mma16816(acc[im][in4 * 2 + 1], ah[im], w[in4][1], w[in4][3]);
                }
        }
    }

    // epilogue: bias + silu, float2 stores
    int gid = lane >> 2;
    int tig = lane & 3;
    #pragma unroll
    for (int im = 0; im < 2; im++) {
        int r0 = lb + warp_m * 32 + im * 16 + gid;
        #pragma unroll
        for (int j = 0; j < 8; j++) {
            int col = nb + warp_n * 64 + j * 8 + tig * 2;
            float b0 = cb[col], b1 = cb[col + 1];
            float2 v0 = make_float2(siluf(acc[im][j][0] + b0), siluf(acc[im][j][1] + b1));
            float2 v1 = make_float2(siluf(acc[im][j][2] + b0), siluf(acc[im][j][3] + b1));
            *(float2*)&g_Bact[(size_t)r0 * EPH + col]       = v0;
            *(float2*)&g_Bact[(size_t)(r0 + 8) * EPH + col] = v1;
        }
    }
}

// ---------------- K3: scan pass 1 (recompute A/Bu inline) + zero ys --------------
__global__ __launch_bounds__(256) void scan_p1_kernel(const float* __restrict__ B) {
    int t = blockIdx.x * blockDim.x + threadIdx.x;   // CHUNKS*NCH = 131072
    g_ys[t] = 0.0f;   // L*H = 131072 floats, 1 per thread

    int c = t & (NCH - 1);
    int ch = t >> 10;
    int base = ch * CHUNK_LEN;
    int ep = c & 31;

    float4 cA = g_cA[c];
    float2 cB = g_cB[c];

    float Pr = 1.0f, Pi = 0.0f, sr = 0.0f, si = 0.0f;
    for (int i = 0; i < CHUNK_LEN; i++) {
        int l = base + i;
        int idx = l * NCH + c;
        float lam = g_Lam[idx];
        float ba  = g_Bact[idx];
        float br = B[l * 64 + ep * 2 + 0];
        float bi = B[l * 64 + ep * 2 + 1];
        float Ar, Ai, bur, bui;
        compute_ABu(lam, ba, br, bi, cA.x, cA.y, cA.z, cB.x, cB.y, Ar, Ai, bur, bui);

        float nsr = Ar * sr - Ai * si + bur;
        float nsi = Ar * si + Ai * sr + bui;
        sr = nsr; si = nsi;
        float npr = Ar * Pr - Ai * Pi;
        float npi = Ar * Pi + Ai * Pr;
        Pr = npr; Pi = npi;
    }
    g_agg[ch * NCH + c] = make_float4(Pr, Pi, sr, si);
}

// ---------------- K4: scan pass 2 (serial over chunks, MLP-prefetched) -----------
__global__ __launch_bounds__(1024) void scan_p2_kernel() {
    int c = threadIdx.x;
    float cr = 0.0f, ci = 0.0f;
    #pragma unroll
    for (int g0 = 0; g0 < CHUNKS; g0 += 8) {
        float4 g[8];
        #pragma unroll
        for (int k = 0; k < 8; k++)
            g[k] = g_agg[(g0 + k) * NCH + c];
        #pragma unroll
        for (int k = 0; k < 8; k++) {
            g_carry[(g0 + k) * NCH + c] = make_float2(cr, ci);
            float nr = g[k].x * cr - g[k].y * ci + g[k].z;
            float ni = g[k].x * ci + g[k].y * cr + g[k].w;
            cr = nr; ci = ni;
        }
    }
}

// ---------------- K5: scan pass 3 (recompute A/Bu, fused ys via atomics) ---------
__global__ __launch_bounds__(256) void scan_p3_kernel(const float* __restrict__ B,
                                                      const float* __restrict__ C) {
    int t = blockIdx.x * blockDim.x + threadIdx.x;
    int c = t & (NCH - 1);
    int ch = t >> 10;
    int base = ch * CHUNK_LEN;
    int ep = c & 31;
    int p = c >> 5;
    int j = c & 31;

    float4 cA = g_cA[c];
    float2 cB = g_cB[c];

    float2 st = g_carry[ch * NCH + c];
    float xr = st.x, xi = st.y;
    for (int i = 0; i < CHUNK_LEN; i++) {
        int l = base + i;
        int idx = l * NCH + c;
        float lam = g_Lam[idx];
        float ba  = g_Bact[idx];
        float br = B[l * 64 + ep * 2 + 0];
        float bi = B[l * 64 + ep * 2 + 1];
        float Ar, Ai, bur, bui;
        compute_ABu(lam, ba, br, bi, cA.x, cA.y, cA.z, cB.x, cB.y, Ar, Ai, bur, bui);

        float nxr = Ar * xr - Ai * xi + bur;
        float nxi = Ar * xi + Ai * xr + bui;
        xr = nxr; xi = nxi;

        float cr = C[l * 64 + p * 2 + 0];
        float ci = C[l * 64 + p * 2 + 1];
        atomicAdd(&g_ys[l * H + j], cr * xr - ci * xi);
    }
}

// ---------------- K8: gating + output projection ---------------------------------
__global__ __launch_bounds__(256) void final_kernel(const float* __restrict__ x,
                                                    const float* __restrict__ Wg,
                                                    const float* __restrict__ bg,
                                                    const float* __restrict__ Wd,
                                                    const float* __restrict__ bd,
                                                    const float* __restrict__ Wo,
                                                    const float* __restrict__ bo,
                                                    float* __restrict__ out) {
    __shared__ float sWg[H * H], sWo[H * H];
    __shared__ float sWd[H], sbg[H], sbo[H];
    __shared__ float sx[8][H], sht[8][H];
    int t = threadIdx.x;
    for (int i = t; i < H * H; i += 256) { sWg[i] = Wg[i]; sWo[i] = Wo[i]; }
    if (t < H) { sWd[t] = Wd[t]; sbg[t] = bg[t]; sbo[t] = bo[t]; }
    int lane = t & 31;
    int w = t >> 5;
    int l = blockIdx.x * 8 + w;
    sx[w][lane] = x[l * H + lane];
    __syncthreads();

    float xg = 0.0f, xd = 0.0f;
    #pragma unroll
    for (int h = 0; h < H; h++) {
        float xv = sx[w][h];
        xg += xv * sWg[h * H + lane];
        xd += xv * sWd[h];
    }
    float gt = siluf(xg + sbg[lane]);
    float d  = log1pf(expf(xd + bd[0]));
    float ysv = g_ys[l * H + lane];
    float xv  = sx[w][lane];
    float ht = (1.0f - gt) * (ysv + d * xv) + gt * xv;
    sht[w][lane] = ht;
    __syncwarp();

    float o = 0.0f;
    #pragma unroll
    for (int h = 0; h < H; h++) o += sht[w][h] * sWo[h * H + lane];
    out[l * H + lane] = o + sbo[lane];
}

// ---------------- launcher -------------------------------------------------------
extern "C" void kernel_launch(void* const* d_in, const int* in_sizes, int n_in,
                              void* d_out, int out_size) {
    const float* x       = (const float*)d_in[0];
    const float* Lre     = (const float*)d_in[1];
    const float* Lim     = (const float*)d_in[2];
    const float* B       = (const float*)d_in[3];
    const float* C       = (const float*)d_in[4];
    const float* logstep = (const float*)d_in[5];
    const float* Wb      = (const float*)d_in[6];
    const float* bb      = (const float*)d_in[7];
    const float* Wl      = (const float*)d_in[8];
    const float* bl      = (const float*)d_in[9];
    const float* cw      = (const float*)d_in[10];
    const float* cb      = (const float*)d_in[11];
    const float* Wg      = (const float*)d_in[12];
    const float* bg      = (const float*)d_in[13];
    const float* Wd      = (const float*)d_in[14];
    const float* bd      = (const float*)d_in[15];
    const float* Wo      = (const float*)d_in[16];
    const float* bo      = (const float*)d_in[17];
    float* out = (float*)d_out;

    cudaFuncSetAttribute(conv_mma_kernel,
                         cudaFuncAttributeMaxDynamicSharedMemorySize, CONV_SMEM);

    precompute_kernel<<<1, 1024>>>(Lre, Lim, logstep);

    dim3 pgrid(L / 32, 4);                    // 512 blocks
    proj_kernel<<<pgrid, 256>>>(x, Wb, bb, Wl, bl);

    dim3 wgrid(KTOT / 32, EPH / 32);          // (128, 32)
    wtrans_kernel<<<wgrid, 256>>>(cw);

    dim3 cgrid(L / GM, EPH / GN);             // (32, 8) = 256 CTAs
    conv_mma_kernel<<<cgrid, 256, CONV_SMEM>>>(cb);

    scan_p1_kernel<<<(CHUNKS * NCH) / 256, 256>>>(B);
    scan_p2_kernel<<<1, 1024>>>();
    scan_p3_kernel<<<(CHUNKS * NCH) / 256, 256>>>(B, C);

    final_kernel<<<L / 8, 256>>>(x, Wg, bg, Wd, bd, Wo, bo, out);
}